// round 5
// baseline (speedup 1.0000x reference)
#include <cuda_runtime.h>
#include <cuda_bf16.h>
#include <cstddef>

// ---------------- problem constants ----------------
#define B_   4
#define S_   1024
#define H_   12
#define DH_  64
#define E_   768
#define DM_  768
#define T_   (B_ * S_)            // 4096 tokens
#define SQK  0.125f               // 1/sqrt(64)
#define WOFF ((size_t)B_ * S_ * H_ * S_)   // 50331648 floats: start of y in d_out

// ---------------- scratch (device globals; no allocation) ----------------
__device__ float g_Q  [B_ * H_ * S_ * DH_];
__device__ float g_K  [B_ * H_ * S_ * DH_];
__device__ float g_V  [B_ * H_ * S_ * DH_];
__device__ float g_ctx[B_ * H_ * S_ * DH_];
__device__ float g_y  [T_ * DM_];
__device__ float g_m  [B_ * H_ * S_];
__device__ float g_l  [B_ * H_ * S_];

// ---------------- packed f32x2 helpers (Blackwell FFMA2 path) ----------------
typedef unsigned long long ull;

__device__ __forceinline__ ull pack2(float lo, float hi) {
    ull r;
    asm("mov.b64 %0, {%1, %2};" : "=l"(r) : "f"(lo), "f"(hi));
    return r;
}
__device__ __forceinline__ void unpack2(ull v, float& lo, float& hi) {
    asm("mov.b64 {%0, %1}, %2;" : "=f"(lo), "=f"(hi) : "l"(v));
}
__device__ __forceinline__ void fma2(ull& c, ull a, ull b) {
    asm("fma.rn.f32x2 %0, %1, %2, %3;" : "=l"(c) : "l"(a), "l"(b), "l"(c));
}
__device__ __forceinline__ void mul2(ull& c, ull a) {
    asm("mul.rn.f32x2 %0, %1, %2;" : "=l"(c) : "l"(c), "l"(a));
}

// 4x4 outer-product accumulate: c[i][j] += a_i * b_j, c packed as 8 x f32x2
__device__ __forceinline__ void mma44(ull c[8], float4 a, float4 b) {
    ull b0 = pack2(b.x, b.y), b1 = pack2(b.z, b.w);
    ull a0 = pack2(a.x, a.x); fma2(c[0], a0, b0); fma2(c[1], a0, b1);
    ull a1 = pack2(a.y, a.y); fma2(c[2], a1, b0); fma2(c[3], a1, b1);
    ull a2 = pack2(a.z, a.z); fma2(c[4], a2, b0); fma2(c[5], a2, b1);
    ull a3 = pack2(a.w, a.w); fma2(c[6], a3, b0); fma2(c[7], a3, b1);
}

// ====================================================================
// K1: QKV projection. grid (T/64, H, 3), block 256.
// One block: 64 tokens x 64 outputs (one head) for Q, K or V.
// ====================================================================
__global__ void __launch_bounds__(256)
qkv_kernel(const float* __restrict__ x,
           const float* __restrict__ Wq, const float* __restrict__ bq,
           const float* __restrict__ Wk, const float* __restrict__ bk,
           const float* __restrict__ Wv, const float* __restrict__ bv)
{
    __shared__ float As[16][64];   // [k][m]
    __shared__ float Bs[16][64];   // [k][n]

    const int mat = blockIdx.z;
    const float* W    = (mat == 0) ? Wq : (mat == 1) ? Wk : Wv;
    const float* bias = (mat == 0) ? bq : (mat == 1) ? bk : bv;
    float* out        = (mat == 0) ? g_Q : (mat == 1) ? g_K : g_V;

    const int h  = blockIdx.y;
    const int t0 = blockIdx.x * 64;
    const int tid = threadIdx.x;
    const int tx = tid & 15, ty = tid >> 4;

    const float* Wh = W + (size_t)h * E_ * DH_;   // [768][64] row-major

    ull c[8];
    #pragma unroll
    for (int i = 0; i < 8; i++) c[i] = 0ull;

    const int am = tid >> 2;            // 0..63
    const int akq = (tid & 3) * 4;      // 0,4,8,12

    for (int k0 = 0; k0 < E_; k0 += 16) {
        // A tile: x[t0+m][k0+akq .. +3]  -> As[k][m]
        float4 av = *(const float4*)(x + (size_t)(t0 + am) * E_ + k0 + akq);
        As[akq + 0][am] = av.x;
        As[akq + 1][am] = av.y;
        As[akq + 2][am] = av.z;
        As[akq + 3][am] = av.w;
        // B tile: contiguous 16x64 block of Wh starting at row k0
        ((float4*)Bs)[tid] = *(const float4*)(Wh + (size_t)k0 * DH_ + tid * 4);
        __syncthreads();

        #pragma unroll
        for (int k = 0; k < 16; k++) {
            float4 a4 = *(const float4*)&As[k][ty * 4];
            float4 b4 = *(const float4*)&Bs[k][tx * 4];
            mma44(c, a4, b4);
        }
        __syncthreads();
    }

    const int b  = t0 >> 10;
    const int s0 = t0 & (S_ - 1);
    const float4 bb = *(const float4*)(bias + h * DH_ + tx * 4);

    #pragma unroll
    for (int i = 0; i < 4; i++) {
        float c0, c1, c2, c3;
        unpack2(c[2 * i],     c0, c1);
        unpack2(c[2 * i + 1], c2, c3);
        const int s = s0 + ty * 4 + i;
        float4 r = make_float4(c0 + bb.x, c1 + bb.y, c2 + bb.z, c3 + bb.w);
        *(float4*)(out + ((size_t)(b * H_ + h) * S_ + s) * DH_ + tx * 4) = r;
    }
}

// ====================================================================
// K2: attention. grid (S/64, H, B), block 256, dynamic smem 66560 B.
// Writes raw scaled scores into d_out weights region; keeps online
// softmax state (m,l) and accumulates ctx = exp(P-m)*V in registers.
// ====================================================================
#define ES_STRIDE 68
#define SMEM_ATTN ((3 * 64 * 64 + 64 * ES_STRIDE) * 4)

__global__ void __launch_bounds__(256)
attn_kernel(float* __restrict__ out)
{
    extern __shared__ float sm[];
    float* Qs = sm;                 // [d][m], 4096
    float* Ks = sm + 4096;          // [d][n], 4096
    float* Vs = sm + 8192;          // [n][d], 4096
    float* Es = sm + 12288;         // [m][n], stride 68

    const int b  = blockIdx.z;
    const int h  = blockIdx.y;
    const int q0 = blockIdx.x * 64;
    const int tid = threadIdx.x;
    const int tx = tid & 15, ty = tid >> 4;

    const size_t head_base = (size_t)(b * H_ + h) * S_ * DH_;
    const float* Qb = g_Q + head_base;
    const float* Kb = g_K + head_base;
    const float* Vb = g_V + head_base;
    float* Cb       = g_ctx + head_base;

    // load Q tile transposed: Qs[d][m]
    #pragma unroll
    for (int r = 0; r < 4; r++) {
        int idx = tid + r * 256;
        int m = idx >> 4, dq = (idx & 15) * 4;
        float4 v = *(const float4*)(Qb + (size_t)(q0 + m) * DH_ + dq);
        Qs[(dq + 0) * 64 + m] = v.x;
        Qs[(dq + 1) * 64 + m] = v.y;
        Qs[(dq + 2) * 64 + m] = v.z;
        Qs[(dq + 3) * 64 + m] = v.w;
    }

    ull cacc[8];
    #pragma unroll
    for (int i = 0; i < 8; i++) cacc[i] = 0ull;
    float mrow[4] = {-1e30f, -1e30f, -1e30f, -1e30f};
    float lrow[4] = {0.f, 0.f, 0.f, 0.f};

    for (int kt = 0; kt < 16; kt++) {
        const int n0 = kt * 64;
        __syncthreads();   // protect Ks/Vs/Es from previous iteration readers

        #pragma unroll
        for (int r = 0; r < 4; r++) {
            int idx = tid + r * 256;
            int n = idx >> 4, dq = (idx & 15) * 4;
            float4 v = *(const float4*)(Kb + (size_t)(n0 + n) * DH_ + dq);
            Ks[(dq + 0) * 64 + n] = v.x;
            Ks[(dq + 1) * 64 + n] = v.y;
            Ks[(dq + 2) * 64 + n] = v.z;
            Ks[(dq + 3) * 64 + n] = v.w;
            ((float4*)Vs)[idx] = ((const float4*)(Vb + (size_t)n0 * DH_))[idx];
        }
        __syncthreads();

        // P = Q K^T (64x64 per block, 4x4 per thread)
        ull p2[8];
        #pragma unroll
        for (int i = 0; i < 8; i++) p2[i] = 0ull;
        #pragma unroll
        for (int d = 0; d < 64; d++) {
            float4 q4 = *(const float4*)(Qs + d * 64 + ty * 4);
            float4 k4 = *(const float4*)(Ks + d * 64 + tx * 4);
            mma44(p2, q4, k4);
        }

        float p[4][4];
        #pragma unroll
        for (int i = 0; i < 4; i++) {
            unpack2(p2[2 * i],     p[i][0], p[i][1]);
            unpack2(p2[2 * i + 1], p[i][2], p[i][3]);
            #pragma unroll
            for (int j = 0; j < 4; j++) p[i][j] *= SQK;
        }

        // stream raw scaled scores to d_out (normalized later by K3)
        #pragma unroll
        for (int i = 0; i < 4; i++) {
            const int s = q0 + ty * 4 + i;
            size_t off = (((size_t)(b * S_ + s)) * H_ + h) * S_ + n0 + tx * 4;
            *(float4*)(out + off) = make_float4(p[i][0], p[i][1], p[i][2], p[i][3]);
        }

        // online softmax update + exp tile to Es
        #pragma unroll
        for (int i = 0; i < 4; i++) {
            float pm = fmaxf(fmaxf(p[i][0], p[i][1]), fmaxf(p[i][2], p[i][3]));
            pm = fmaxf(pm, __shfl_xor_sync(0xffffffffu, pm, 1));
            pm = fmaxf(pm, __shfl_xor_sync(0xffffffffu, pm, 2));
            pm = fmaxf(pm, __shfl_xor_sync(0xffffffffu, pm, 4));
            pm = fmaxf(pm, __shfl_xor_sync(0xffffffffu, pm, 8));
            float mnew = fmaxf(mrow[i], pm);
            float f = __expf(mrow[i] - mnew);
            mrow[i] = mnew;
            float e0 = __expf(p[i][0] - mnew);
            float e1 = __expf(p[i][1] - mnew);
            float e2 = __expf(p[i][2] - mnew);
            float e3 = __expf(p[i][3] - mnew);
            float rs = (e0 + e1) + (e2 + e3);
            rs += __shfl_xor_sync(0xffffffffu, rs, 1);
            rs += __shfl_xor_sync(0xffffffffu, rs, 2);
            rs += __shfl_xor_sync(0xffffffffu, rs, 4);
            rs += __shfl_xor_sync(0xffffffffu, rs, 8);
            lrow[i] = lrow[i] * f + rs;
            ull f2 = pack2(f, f);
            mul2(cacc[2 * i], f2);
            mul2(cacc[2 * i + 1], f2);
            *(float4*)(Es + (ty * 4 + i) * ES_STRIDE + tx * 4) =
                make_float4(e0, e1, e2, e3);
        }
        __syncthreads();

        // ctx += E * V
        #pragma unroll 4
        for (int n = 0; n < 64; n++) {
            float4 v4 = *(const float4*)(Vs + n * 64 + tx * 4);
            ull b0 = pack2(v4.x, v4.y), b1 = pack2(v4.z, v4.w);
            #pragma unroll
            for (int i = 0; i < 4; i++) {
                float e = Es[(ty * 4 + i) * ES_STRIDE + n];
                ull a2 = pack2(e, e);
                fma2(cacc[2 * i], a2, b0);
                fma2(cacc[2 * i + 1], a2, b1);
            }
        }
    }

    // epilogue: ctx / l, store ctx and (m,l)
    #pragma unroll
    for (int i = 0; i < 4; i++) {
        const int s = q0 + ty * 4 + i;
        float inv = 1.0f / lrow[i];
        float c0, c1, c2, c3;
        unpack2(cacc[2 * i],     c0, c1);
        unpack2(cacc[2 * i + 1], c2, c3);
        *(float4*)(Cb + (size_t)s * DH_ + tx * 4) =
            make_float4(c0 * inv, c1 * inv, c2 * inv, c3 * inv);
        if (tx == 0) {
            g_m[(b * H_ + h) * S_ + s] = mrow[i];
            g_l[(b * H_ + h) * S_ + s] = lrow[i];
        }
    }
}

// ====================================================================
// K3: in-place normalization of the weights region of d_out.
// grid B*S*H, block 256, 4 floats/thread.
// ====================================================================
__global__ void __launch_bounds__(256)
normw_kernel(float* __restrict__ out)
{
    const int row = blockIdx.x;          // (b*S + s)*H + h
    const int h  = row % H_;
    const int bs = row / H_;
    const int s  = bs & (S_ - 1);
    const int b  = bs >> 10;
    const float m    = g_m[(b * H_ + h) * S_ + s];
    const float invl = 1.0f / g_l[(b * H_ + h) * S_ + s];

    size_t base = (size_t)row * S_ + threadIdx.x * 4;
    float4 p = *(float4*)(out + base);
    p.x = __expf(p.x - m) * invl;
    p.y = __expf(p.y - m) * invl;
    p.z = __expf(p.z - m) * invl;
    p.w = __expf(p.w - m) * invl;
    *(float4*)(out + base) = p;
}

// ====================================================================
// K4: output dense. grid (T/64, DM/64), block 256.
// A is ctx gathered in head-interleaved order; B is Wd [in][out].
// ====================================================================
__global__ void __launch_bounds__(256)
dense_kernel(const float* __restrict__ Wd, const float* __restrict__ bd)
{
    __shared__ float As[16][64];   // [k][m]
    __shared__ float Bs[16][64];   // [k][n]

    const int t0 = blockIdx.x * 64;
    const int n0 = blockIdx.y * 64;
    const int tid = threadIdx.x;
    const int tx = tid & 15, ty = tid >> 4;
    const int b  = t0 >> 10;
    const int s0 = t0 & (S_ - 1);

    ull c[8];
    #pragma unroll
    for (int i = 0; i < 8; i++) c[i] = 0ull;

    const int am = tid >> 2;
    const int akq = (tid & 3) * 4;
    const int bk = tid >> 4;
    const int bnq = (tid & 15) * 4;

    for (int k0 = 0; k0 < DM_; k0 += 16) {
        const int hh = k0 >> 6, d0 = k0 & 63;
        float4 av = *(const float4*)(g_ctx +
            ((size_t)(b * H_ + hh) * S_ + s0 + am) * DH_ + d0 + akq);
        As[akq + 0][am] = av.x;
        As[akq + 1][am] = av.y;
        As[akq + 2][am] = av.z;
        As[akq + 3][am] = av.w;
        *(float4*)&Bs[bk][bnq] =
            *(const float4*)(Wd + (size_t)(k0 + bk) * DM_ + n0 + bnq);
        __syncthreads();

        #pragma unroll
        for (int k = 0; k < 16; k++) {
            float4 a4 = *(const float4*)&As[k][ty * 4];
            float4 b4 = *(const float4*)&Bs[k][tx * 4];
            mma44(c, a4, b4);
        }
        __syncthreads();
    }

    const float4 bb = *(const float4*)(bd + n0 + tx * 4);
    #pragma unroll
    for (int i = 0; i < 4; i++) {
        float c0, c1, c2, c3;
        unpack2(c[2 * i],     c0, c1);
        unpack2(c[2 * i + 1], c2, c3);
        *(float4*)(g_y + (size_t)(t0 + ty * 4 + i) * DM_ + n0 + tx * 4) =
            make_float4(c0 + bb.x, c1 + bb.y, c2 + bb.z, c3 + bb.w);
    }
}

// ====================================================================
// K5: LayerNorm. grid T, block 256. Two-pass over one 768-row in smem.
// ====================================================================
__global__ void __launch_bounds__(256)
ln_kernel(const float* __restrict__ gamma, const float* __restrict__ beta,
          float* __restrict__ out)
{
    __shared__ float row[DM_];
    __shared__ float red[8];

    const int t = blockIdx.x;
    const int tid = threadIdx.x;

    float s = 0.f;
    #pragma unroll
    for (int j = 0; j < 3; j++) {
        float v = g_y[(size_t)t * DM_ + tid + j * 256];
        row[tid + j * 256] = v;
        s += v;
    }
    #pragma unroll
    for (int o = 16; o > 0; o >>= 1) s += __shfl_xor_sync(0xffffffffu, s, o);
    if ((tid & 31) == 0) red[tid >> 5] = s;
    __syncthreads();
    float tot = red[0];
    #pragma unroll
    for (int i = 1; i < 8; i++) tot += red[i];
    const float mu = tot * (1.0f / DM_);
    __syncthreads();   // before reusing red

    float vs = 0.f;
    #pragma unroll
    for (int j = 0; j < 3; j++) {
        float d = row[tid + j * 256] - mu;
        vs += d * d;
    }
    #pragma unroll
    for (int o = 16; o > 0; o >>= 1) vs += __shfl_xor_sync(0xffffffffu, vs, o);
    if ((tid & 31) == 0) red[tid >> 5] = vs;
    __syncthreads();
    float tv = red[0];
    #pragma unroll
    for (int i = 1; i < 8; i++) tv += red[i];
    const float scale = rsqrtf(tv * (1.0f / DM_) + 1e-12f);

    #pragma unroll
    for (int j = 0; j < 3; j++) {
        const int idx = tid + j * 256;
        out[WOFF + (size_t)t * DM_ + idx] =
            (row[idx] - mu) * scale * gamma[idx] + beta[idx];
    }
}

// ====================================================================
// launch
// ====================================================================
extern "C" void kernel_launch(void* const* d_in, const int* in_sizes, int n_in,
                              void* d_out, int out_size)
{
    (void)in_sizes; (void)n_in; (void)out_size;
    const float* x     = (const float*)d_in[0];
    const float* Wq    = (const float*)d_in[1];
    const float* bq    = (const float*)d_in[2];
    const float* Wk    = (const float*)d_in[3];
    const float* bk    = (const float*)d_in[4];
    const float* Wv    = (const float*)d_in[5];
    const float* bv    = (const float*)d_in[6];
    const float* Wd    = (const float*)d_in[7];
    const float* bd    = (const float*)d_in[8];
    const float* gamma = (const float*)d_in[9];
    const float* beta  = (const float*)d_in[10];
    float* out = (float*)d_out;

    qkv_kernel<<<dim3(T_ / 64, H_, 3), 256>>>(x, Wq, bq, Wk, bk, Wv, bv);

    cudaFuncSetAttribute(attn_kernel,
                         cudaFuncAttributeMaxDynamicSharedMemorySize, SMEM_ATTN);
    attn_kernel<<<dim3(S_ / 64, H_, B_), 256, SMEM_ATTN>>>(out);

    normw_kernel<<<B_ * S_ * H_, 256>>>(out);

    dense_kernel<<<dim3(T_ / 64, DM_ / 64), 256>>>(Wd, bd);

    ln_kernel<<<T_, 256>>>(gamma, beta, out);
}

// round 7
// speedup vs baseline: 1.0250x; 1.0250x over previous
#include <cuda_runtime.h>
#include <cuda_bf16.h>
#include <cstdint>
#include <cstddef>

// ---------------- problem constants ----------------
#define B_   4
#define S_   1024
#define H_   12
#define DH_  64
#define E_   768
#define DM_  768
#define T_   (B_ * S_)            // 4096 tokens
#define SQK  0.125f               // 1/sqrt(64)
#define WOFF ((size_t)B_ * S_ * H_ * S_)   // start of y in d_out

// ---------------- scratch (device globals; no allocation) ----------------
__device__ float g_Q  [B_ * H_ * S_ * DH_];
__device__ float g_K  [B_ * H_ * S_ * DH_];
__device__ float g_V  [B_ * H_ * S_ * DH_];
__device__ float g_ctx[B_ * H_ * S_ * DH_];
__device__ float g_y  [T_ * DM_];
__device__ float g_m  [B_ * H_ * S_];
__device__ float g_l  [B_ * H_ * S_];

// ---------------- packed f32x2 helpers (attn kernel) ----------------
typedef unsigned long long ull;

__device__ __forceinline__ ull pack2(float lo, float hi) {
    ull r;
    asm("mov.b64 %0, {%1, %2};" : "=l"(r) : "f"(lo), "f"(hi));
    return r;
}
__device__ __forceinline__ void unpack2(ull v, float& lo, float& hi) {
    asm("mov.b64 {%0, %1}, %2;" : "=f"(lo), "=f"(hi) : "l"(v));
}
__device__ __forceinline__ void fma2(ull& c, ull a, ull b) {
    asm("fma.rn.f32x2 %0, %1, %2, %3;" : "=l"(c) : "l"(a), "l"(b), "l"(c));
}
__device__ __forceinline__ void mul2(ull& c, ull a) {
    asm("mul.rn.f32x2 %0, %1, %2;" : "=l"(c) : "l"(c), "l"(a));
}
__device__ __forceinline__ void mma44(ull c[8], float4 a, float4 b) {
    ull b0 = pack2(b.x, b.y), b1 = pack2(b.z, b.w);
    ull a0 = pack2(a.x, a.x); fma2(c[0], a0, b0); fma2(c[1], a0, b1);
    ull a1 = pack2(a.y, a.y); fma2(c[2], a1, b0); fma2(c[3], a1, b1);
    ull a2 = pack2(a.z, a.z); fma2(c[4], a2, b0); fma2(c[5], a2, b1);
    ull a3 = pack2(a.w, a.w); fma2(c[6], a3, b0); fma2(c[7], a3, b1);
}

// ---------------- mma.sync / ldmatrix helpers (compute_100-safe) ----------------
__device__ __forceinline__ uint32_t smem_u32(const void* p) {
    uint32_t a;
    asm("{ .reg .u64 t; cvta.to.shared.u64 t, %1; cvt.u32.u64 %0, t; }"
        : "=r"(a) : "l"(p));
    return a;
}

__device__ __forceinline__ void ldsm4(uint32_t r[4], uint32_t addr) {
    asm volatile("ldmatrix.sync.aligned.m8n8.x4.shared.b16 {%0,%1,%2,%3}, [%4];"
                 : "=r"(r[0]), "=r"(r[1]), "=r"(r[2]), "=r"(r[3]) : "r"(addr));
}

__device__ __forceinline__ void mma_bf16(float d[4], const uint32_t a[4],
                                         uint32_t b0, uint32_t b1) {
    asm volatile(
        "mma.sync.aligned.m16n8k16.row.col.f32.bf16.bf16.f32 "
        "{%0,%1,%2,%3}, {%4,%5,%6,%7}, {%8,%9}, {%0,%1,%2,%3};"
        : "+f"(d[0]), "+f"(d[1]), "+f"(d[2]), "+f"(d[3])
        : "r"(a[0]), "r"(a[1]), "r"(a[2]), "r"(a[3]), "r"(b0), "r"(b1));
}

// split a float pair into packed bf16 hi and bf16 lo (v ≈ hi + lo)
__device__ __forceinline__ void split2(float v0, float v1,
                                       uint32_t& hi, uint32_t& lo) {
    __nv_bfloat16 h0 = __float2bfloat16_rn(v0);
    __nv_bfloat16 h1 = __float2bfloat16_rn(v1);
    __nv_bfloat16 l0 = __float2bfloat16_rn(v0 - __bfloat162float(h0));
    __nv_bfloat16 l1 = __float2bfloat16_rn(v1 - __bfloat162float(h1));
    hi = (uint32_t)__bfloat16_as_ushort(h0) |
         ((uint32_t)__bfloat16_as_ushort(h1) << 16);
    lo = (uint32_t)__bfloat16_as_ushort(l0) |
         ((uint32_t)__bfloat16_as_ushort(l1) << 16);
}

// smem tile geometry: 128 rows x 64 bf16, row stride 72 halves (144 B)
#define STRB   144
#define TILE_B (128 * STRB)          // 18432 B per tile
#define SMEM_GEMM (4 * TILE_B)       // Ah, Al, Bh, Bl = 73728 B

// ====================================================================
// GEMM core (shared by qkv_mma and dense_mma): runs the per-chunk
// ldmatrix + 3-term split mma over smem tiles already populated.
// acc[mi][ni][4]; warp tile = 32 (M) x 64 (N); block = 128x128.
// ====================================================================
struct FragBase { uint32_t a, b; };

__device__ __forceinline__ FragBase frag_base(uint32_t smu, int lane, int wm, int wn) {
    FragBase f;
    f.a = smu + (uint32_t)((wm * 32 + (lane & 15)) * STRB + ((lane >> 4) & 1) * 16);
    f.b = smu + 2u * TILE_B +
          (uint32_t)((wn * 64 + (lane & 7) + ((lane & 16) >> 1)) * STRB + (lane & 8) * 2);
    return f;
}

__device__ __forceinline__ void gemm_chunk(float acc[2][8][4], FragBase f) {
    #pragma unroll
    for (int k16 = 0; k16 < 4; ++k16) {
        uint32_t ah[2][4], al[2][4];
        #pragma unroll
        for (int mi = 0; mi < 2; ++mi) {
            uint32_t addr = f.a + (uint32_t)(mi * 16 * STRB + k16 * 32);
            ldsm4(ah[mi], addr);
            ldsm4(al[mi], addr + TILE_B);
        }
        #pragma unroll
        for (int np = 0; np < 4; ++np) {
            uint32_t bh[4], bl[4];
            uint32_t addr = f.b + (uint32_t)(np * 16 * STRB + k16 * 32);
            ldsm4(bh, addr);
            ldsm4(bl, addr + TILE_B);
            #pragma unroll
            for (int mi = 0; mi < 2; ++mi) {
                #pragma unroll
                for (int j = 0; j < 2; ++j) {
                    float* d = acc[mi][np * 2 + j];
                    mma_bf16(d, ah[mi], bh[2 * j], bh[2 * j + 1]);
                    mma_bf16(d, ah[mi], bl[2 * j], bl[2 * j + 1]);
                    mma_bf16(d, al[mi], bh[2 * j], bh[2 * j + 1]);
                }
            }
        }
    }
}

// ====================================================================
// K1: QKV projection via mma.sync bf16 split-3.
// grid (32, 6, 3), block 256. Block tile: 128 tokens x 128 cols
// (two heads). K = 768 in 12 chunks of 64.
// ====================================================================
__global__ void __launch_bounds__(256)
qkv_mma(const float* __restrict__ x,
        const float* __restrict__ Wq, const float* __restrict__ bq,
        const float* __restrict__ Wk, const float* __restrict__ bk,
        const float* __restrict__ Wv, const float* __restrict__ bv)
{
    extern __shared__ char sm[];
    char* Ah = sm;
    char* Al = sm + TILE_B;
    char* Bh = sm + 2 * TILE_B;
    char* Bl = sm + 3 * TILE_B;

    const int tid = threadIdx.x, lane = tid & 31, wid = tid >> 5;
    const int wm = wid & 3, wn = wid >> 2;

    const int mat = blockIdx.z;
    const float* W    = (mat == 0) ? Wq : (mat == 1) ? Wk : Wv;
    const float* bias = (mat == 0) ? bq : (mat == 1) ? bk : bv;
    float* outp       = (mat == 0) ? g_Q : (mat == 1) ? g_K : g_V;

    const int t0 = blockIdx.x * 128;
    const int n0 = blockIdx.y * 128;
    const int h0 = n0 >> 6;

    float acc[2][8][4];
    #pragma unroll
    for (int i = 0; i < 2; ++i)
        #pragma unroll
        for (int j = 0; j < 8; ++j)
            #pragma unroll
            for (int k = 0; k < 4; ++k) acc[i][j][k] = 0.f;

    const FragBase fb = frag_base(smem_u32(sm), lane, wm, wn);

    for (int c = 0; c < 12; ++c) {
        const int k0 = c * 64;
        __syncthreads();
        // A tile: x[t0+m][k0..k0+63] -> hi/lo bf16
        #pragma unroll
        for (int r = 0; r < 8; ++r) {
            int idx = tid + r * 256;
            int m = idx >> 4, kq = (idx & 15) * 4;
            float4 v = *(const float4*)(x + (size_t)(t0 + m) * E_ + k0 + kq);
            uint32_t h01, l01, h23, l23;
            split2(v.x, v.y, h01, l01);
            split2(v.z, v.w, h23, l23);
            *(uint2*)(Ah + m * STRB + kq * 2) = make_uint2(h01, h23);
            *(uint2*)(Al + m * STRB + kq * 2) = make_uint2(l01, l23);
        }
        // B tile: B[n][k] = W[h][k0+k][d], n = (h-h0)*64 + d
        #pragma unroll
        for (int r = 0; r < 8; ++r) {
            int idx = tid + r * 256;
            int k = idx >> 5, nq = (idx & 31) * 4;
            int h = h0 + (nq >> 6), d = nq & 63;
            float4 v = *(const float4*)(W + ((size_t)h * E_ + k0 + k) * DH_ + d);
            float vv[4] = {v.x, v.y, v.z, v.w};
            #pragma unroll
            for (int j = 0; j < 4; ++j) {
                __nv_bfloat16 hb = __float2bfloat16_rn(vv[j]);
                __nv_bfloat16 lb = __float2bfloat16_rn(vv[j] - __bfloat162float(hb));
                *(__nv_bfloat16*)(Bh + (nq + j) * STRB + k * 2) = hb;
                *(__nv_bfloat16*)(Bl + (nq + j) * STRB + k * 2) = lb;
            }
        }
        __syncthreads();
        gemm_chunk(acc, fb);
    }

    // epilogue: add bias, scatter to [B,H,S,64]
    #pragma unroll
    for (int mi = 0; mi < 2; ++mi) {
        #pragma unroll
        for (int ni = 0; ni < 8; ++ni) {
            const int cl = wn * 64 + ni * 8 + (lane & 3) * 2;
            const int ng = n0 + cl;
            const int h = ng >> 6, d = ng & 63;
            const float b0v = bias[h * DH_ + d];
            const float b1v = bias[h * DH_ + d + 1];
            #pragma unroll
            for (int r8 = 0; r8 < 2; ++r8) {
                const int t = t0 + wm * 32 + mi * 16 + (lane >> 2) + r8 * 8;
                const int bb = t >> 10, ss = t & (S_ - 1);
                float2 o = make_float2(acc[mi][ni][2 * r8] + b0v,
                                       acc[mi][ni][2 * r8 + 1] + b1v);
                *(float2*)(outp + ((size_t)(bb * H_ + h) * S_ + ss) * DH_ + d) = o;
            }
        }
    }
}

// ====================================================================
// K4: output dense via mma.sync bf16 split-3. grid (32, 6), block 256.
// A = gathered ctx (chunk c == head c), B = Wd[k][n].
// ====================================================================
__global__ void __launch_bounds__(256)
dense_mma(const float* __restrict__ Wd, const float* __restrict__ bd)
{
    extern __shared__ char sm[];
    char* Ah = sm;
    char* Al = sm + TILE_B;
    char* Bh = sm + 2 * TILE_B;
    char* Bl = sm + 3 * TILE_B;

    const int tid = threadIdx.x, lane = tid & 31, wid = tid >> 5;
    const int wm = wid & 3, wn = wid >> 2;

    const int t0 = blockIdx.x * 128;
    const int n0 = blockIdx.y * 128;

    float acc[2][8][4];
    #pragma unroll
    for (int i = 0; i < 2; ++i)
        #pragma unroll
        for (int j = 0; j < 8; ++j)
            #pragma unroll
            for (int k = 0; k < 4; ++k) acc[i][j][k] = 0.f;

    const FragBase fb = frag_base(smem_u32(sm), lane, wm, wn);

    for (int c = 0; c < 12; ++c) {
        const int k0 = c * 64;
        __syncthreads();
        // A tile: gathered ctx; chunk c maps exactly to head c
        #pragma unroll
        for (int r = 0; r < 8; ++r) {
            int idx = tid + r * 256;
            int m = idx >> 4, kq = (idx & 15) * 4;
            int t = t0 + m, bb = t >> 10, ss = t & (S_ - 1);
            float4 v = *(const float4*)(g_ctx +
                ((size_t)(bb * H_ + c) * S_ + ss) * DH_ + kq);
            uint32_t h01, l01, h23, l23;
            split2(v.x, v.y, h01, l01);
            split2(v.z, v.w, h23, l23);
            *(uint2*)(Ah + m * STRB + kq * 2) = make_uint2(h01, h23);
            *(uint2*)(Al + m * STRB + kq * 2) = make_uint2(l01, l23);
        }
        // B tile: B[n][k] = Wd[k0+k][n0+n]
        #pragma unroll
        for (int r = 0; r < 8; ++r) {
            int idx = tid + r * 256;
            int k = idx >> 5, nq = (idx & 31) * 4;
            float4 v = *(const float4*)(Wd + (size_t)(k0 + k) * DM_ + n0 + nq);
            float vv[4] = {v.x, v.y, v.z, v.w};
            #pragma unroll
            for (int j = 0; j < 4; ++j) {
                __nv_bfloat16 hb = __float2bfloat16_rn(vv[j]);
                __nv_bfloat16 lb = __float2bfloat16_rn(vv[j] - __bfloat162float(hb));
                *(__nv_bfloat16*)(Bh + (nq + j) * STRB + k * 2) = hb;
                *(__nv_bfloat16*)(Bl + (nq + j) * STRB + k * 2) = lb;
            }
        }
        __syncthreads();
        gemm_chunk(acc, fb);
    }

    #pragma unroll
    for (int mi = 0; mi < 2; ++mi) {
        #pragma unroll
        for (int ni = 0; ni < 8; ++ni) {
            const int cl = wn * 64 + ni * 8 + (lane & 3) * 2;
            const float b0v = bd[n0 + cl];
            const float b1v = bd[n0 + cl + 1];
            #pragma unroll
            for (int r8 = 0; r8 < 2; ++r8) {
                const int t = t0 + wm * 32 + mi * 16 + (lane >> 2) + r8 * 8;
                float2 o = make_float2(acc[mi][ni][2 * r8] + b0v,
                                       acc[mi][ni][2 * r8 + 1] + b1v);
                *(float2*)(g_y + (size_t)t * DM_ + n0 + cl) = o;
            }
        }
    }
}

// ====================================================================
// K2: attention (unchanged, known-passing fp32 f32x2 path).
// ====================================================================
#define ES_STRIDE 68
#define SMEM_ATTN ((3 * 64 * 64 + 64 * ES_STRIDE) * 4)

__global__ void __launch_bounds__(256)
attn_kernel(float* __restrict__ out)
{
    extern __shared__ float smf[];
    float* Qs = smf;
    float* Ks = smf + 4096;
    float* Vs = smf + 8192;
    float* Es = smf + 12288;

    const int b  = blockIdx.z;
    const int h  = blockIdx.y;
    const int q0 = blockIdx.x * 64;
    const int tid = threadIdx.x;
    const int tx = tid & 15, ty = tid >> 4;

    const size_t head_base = (size_t)(b * H_ + h) * S_ * DH_;
    const float* Qb = g_Q + head_base;
    const float* Kb = g_K + head_base;
    const float* Vb = g_V + head_base;
    float* Cb       = g_ctx + head_base;

    #pragma unroll
    for (int r = 0; r < 4; r++) {
        int idx = tid + r * 256;
        int m = idx >> 4, dq = (idx & 15) * 4;
        float4 v = *(const float4*)(Qb + (size_t)(q0 + m) * DH_ + dq);
        Qs[(dq + 0) * 64 + m] = v.x;
        Qs[(dq + 1) * 64 + m] = v.y;
        Qs[(dq + 2) * 64 + m] = v.z;
        Qs[(dq + 3) * 64 + m] = v.w;
    }

    ull cacc[8];
    #pragma unroll
    for (int i = 0; i < 8; i++) cacc[i] = 0ull;
    float mrow[4] = {-1e30f, -1e30f, -1e30f, -1e30f};
    float lrow[4] = {0.f, 0.f, 0.f, 0.f};

    for (int kt = 0; kt < 16; kt++) {
        const int n0 = kt * 64;
        __syncthreads();

        #pragma unroll
        for (int r = 0; r < 4; r++) {
            int idx = tid + r * 256;
            int n = idx >> 4, dq = (idx & 15) * 4;
            float4 v = *(const float4*)(Kb + (size_t)(n0 + n) * DH_ + dq);
            Ks[(dq + 0) * 64 + n] = v.x;
            Ks[(dq + 1) * 64 + n] = v.y;
            Ks[(dq + 2) * 64 + n] = v.z;
            Ks[(dq + 3) * 64 + n] = v.w;
            ((float4*)Vs)[idx] = ((const float4*)(Vb + (size_t)n0 * DH_))[idx];
        }
        __syncthreads();

        ull p2[8];
        #pragma unroll
        for (int i = 0; i < 8; i++) p2[i] = 0ull;
        #pragma unroll
        for (int d = 0; d < 64; d++) {
            float4 q4 = *(const float4*)(Qs + d * 64 + ty * 4);
            float4 k4 = *(const float4*)(Ks + d * 64 + tx * 4);
            mma44(p2, q4, k4);
        }

        float p[4][4];
        #pragma unroll
        for (int i = 0; i < 4; i++) {
            unpack2(p2[2 * i],     p[i][0], p[i][1]);
            unpack2(p2[2 * i + 1], p[i][2], p[i][3]);
            #pragma unroll
            for (int j = 0; j < 4; j++) p[i][j] *= SQK;
        }

        #pragma unroll
        for (int i = 0; i < 4; i++) {
            const int s = q0 + ty * 4 + i;
            size_t off = (((size_t)(b * S_ + s)) * H_ + h) * S_ + n0 + tx * 4;
            *(float4*)(out + off) = make_float4(p[i][0], p[i][1], p[i][2], p[i][3]);
        }

        #pragma unroll
        for (int i = 0; i < 4; i++) {
            float pm = fmaxf(fmaxf(p[i][0], p[i][1]), fmaxf(p[i][2], p[i][3]));
            pm = fmaxf(pm, __shfl_xor_sync(0xffffffffu, pm, 1));
            pm = fmaxf(pm, __shfl_xor_sync(0xffffffffu, pm, 2));
            pm = fmaxf(pm, __shfl_xor_sync(0xffffffffu, pm, 4));
            pm = fmaxf(pm, __shfl_xor_sync(0xffffffffu, pm, 8));
            float mnew = fmaxf(mrow[i], pm);
            float f = __expf(mrow[i] - mnew);
            mrow[i] = mnew;
            float e0 = __expf(p[i][0] - mnew);
            float e1 = __expf(p[i][1] - mnew);
            float e2 = __expf(p[i][2] - mnew);
            float e3 = __expf(p[i][3] - mnew);
            float rs = (e0 + e1) + (e2 + e3);
            rs += __shfl_xor_sync(0xffffffffu, rs, 1);
            rs += __shfl_xor_sync(0xffffffffu, rs, 2);
            rs += __shfl_xor_sync(0xffffffffu, rs, 4);
            rs += __shfl_xor_sync(0xffffffffu, rs, 8);
            lrow[i] = lrow[i] * f + rs;
            ull f2 = pack2(f, f);
            mul2(cacc[2 * i], f2);
            mul2(cacc[2 * i + 1], f2);
            *(float4*)(Es + (ty * 4 + i) * ES_STRIDE + tx * 4) =
                make_float4(e0, e1, e2, e3);
        }
        __syncthreads();

        #pragma unroll 4
        for (int n = 0; n < 64; n++) {
            float4 v4 = *(const float4*)(Vs + n * 64 + tx * 4);
            ull b0 = pack2(v4.x, v4.y), b1 = pack2(v4.z, v4.w);
            #pragma unroll
            for (int i = 0; i < 4; i++) {
                float e = Es[(ty * 4 + i) * ES_STRIDE + n];
                ull a2 = pack2(e, e);
                fma2(cacc[2 * i], a2, b0);
                fma2(cacc[2 * i + 1], a2, b1);
            }
        }
    }

    #pragma unroll
    for (int i = 0; i < 4; i++) {
        const int s = q0 + ty * 4 + i;
        float inv = 1.0f / lrow[i];
        float c0, c1, c2, c3;
        unpack2(cacc[2 * i],     c0, c1);
        unpack2(cacc[2 * i + 1], c2, c3);
        *(float4*)(Cb + (size_t)s * DH_ + tx * 4) =
            make_float4(c0 * inv, c1 * inv, c2 * inv, c3 * inv);
        if (tx == 0) {
            g_m[(b * H_ + h) * S_ + s] = mrow[i];
            g_l[(b * H_ + h) * S_ + s] = lrow[i];
        }
    }
}

// ====================================================================
// K3: in-place normalization of the weights region of d_out.
// ====================================================================
__global__ void __launch_bounds__(256)
normw_kernel(float* __restrict__ out)
{
    const int row = blockIdx.x;
    const int h  = row % H_;
    const int bs = row / H_;
    const int s  = bs & (S_ - 1);
    const int b  = bs >> 10;
    const float m    = g_m[(b * H_ + h) * S_ + s];
    const float invl = 1.0f / g_l[(b * H_ + h) * S_ + s];

    size_t base = (size_t)row * S_ + threadIdx.x * 4;
    float4 p = *(float4*)(out + base);
    p.x = __expf(p.x - m) * invl;
    p.y = __expf(p.y - m) * invl;
    p.z = __expf(p.z - m) * invl;
    p.w = __expf(p.w - m) * invl;
    *(float4*)(out + base) = p;
}

// ====================================================================
// K5: LayerNorm. grid T, block 256.
// ====================================================================
__global__ void __launch_bounds__(256)
ln_kernel(const float* __restrict__ gamma, const float* __restrict__ beta,
          float* __restrict__ out)
{
    __shared__ float row[DM_];
    __shared__ float red[8];

    const int t = blockIdx.x;
    const int tid = threadIdx.x;

    float s = 0.f;
    #pragma unroll
    for (int j = 0; j < 3; j++) {
        float v = g_y[(size_t)t * DM_ + tid + j * 256];
        row[tid + j * 256] = v;
        s += v;
    }
    #pragma unroll
    for (int o = 16; o > 0; o >>= 1) s += __shfl_xor_sync(0xffffffffu, s, o);
    if ((tid & 31) == 0) red[tid >> 5] = s;
    __syncthreads();
    float tot = red[0];
    #pragma unroll
    for (int i = 1; i < 8; i++) tot += red[i];
    const float mu = tot * (1.0f / DM_);
    __syncthreads();

    float vs = 0.f;
    #pragma unroll
    for (int j = 0; j < 3; j++) {
        float d = row[tid + j * 256] - mu;
        vs += d * d;
    }
    #pragma unroll
    for (int o = 16; o > 0; o >>= 1) vs += __shfl_xor_sync(0xffffffffu, vs, o);
    if ((tid & 31) == 0) red[tid >> 5] = vs;
    __syncthreads();
    float tv = red[0];
    #pragma unroll
    for (int i = 1; i < 8; i++) tv += red[i];
    const float scale = rsqrtf(tv * (1.0f / DM_) + 1e-12f);

    #pragma unroll
    for (int j = 0; j < 3; j++) {
        const int idx = tid + j * 256;
        out[WOFF + (size_t)t * DM_ + idx] =
            (row[idx] - mu) * scale * gamma[idx] + beta[idx];
    }
}

// ====================================================================
// launch
// ====================================================================
extern "C" void kernel_launch(void* const* d_in, const int* in_sizes, int n_in,
                              void* d_out, int out_size)
{
    (void)in_sizes; (void)n_in; (void)out_size;
    const float* x     = (const float*)d_in[0];
    const float* Wq    = (const float*)d_in[1];
    const float* bq    = (const float*)d_in[2];
    const float* Wk    = (const float*)d_in[3];
    const float* bk    = (const float*)d_in[4];
    const float* Wv    = (const float*)d_in[5];
    const float* bv    = (const float*)d_in[6];
    const float* Wd    = (const float*)d_in[7];
    const float* bd    = (const float*)d_in[8];
    const float* gamma = (const float*)d_in[9];
    const float* beta  = (const float*)d_in[10];
    float* out = (float*)d_out;

    cudaFuncSetAttribute(qkv_mma,
                         cudaFuncAttributeMaxDynamicSharedMemorySize, SMEM_GEMM);
    cudaFuncSetAttribute(dense_mma,
                         cudaFuncAttributeMaxDynamicSharedMemorySize, SMEM_GEMM);
    cudaFuncSetAttribute(attn_kernel,
                         cudaFuncAttributeMaxDynamicSharedMemorySize, SMEM_ATTN);

    qkv_mma<<<dim3(T_ / 128, DM_ / 128, 3), 256, SMEM_GEMM>>>(
        x, Wq, bq, Wk, bk, Wv, bv);

    attn_kernel<<<dim3(S_ / 64, H_, B_), 256, SMEM_ATTN>>>(out);

    normw_kernel<<<B_ * S_ * H_, 256>>>(out);

    dense_mma<<<dim3(T_ / 128, DM_ / 128), 256, SMEM_GEMM>>>(Wd, bd);

    ln_kernel<<<T_, 256>>>(gamma, beta, out);
}

// round 9
// speedup vs baseline: 1.4155x; 1.3811x over previous
#include <cuda_runtime.h>
#include <cuda_bf16.h>
#include <cstdint>
#include <cstddef>

// ---------------- problem constants ----------------
#define B_   4
#define S_   1024
#define H_   12
#define DH_  64
#define E_   768
#define DM_  768
#define T_   (B_ * S_)            // 4096 tokens
#define KP   2304                 // triple-expanded K: (ah,ah,al) x (bh,bl,bh)
#define SQK  0.125f               // 1/sqrt(64)
#define WOFF ((size_t)B_ * S_ * H_ * S_)   // start of y in d_out

// ---------------- scratch (device globals; no allocation) ----------------
__device__ float g_Q [B_ * H_ * S_ * DH_];
__device__ float g_K [B_ * H_ * S_ * DH_];
__device__ float g_V [B_ * H_ * S_ * DH_];
__device__ float g_y [T_ * DM_];
__device__ float g_m [B_ * H_ * S_];
__device__ float g_l [B_ * H_ * S_];
// triple-expanded bf16 operands
__device__ __nv_bfloat16 g_xi [T_ * KP];            // x tokens   [t][k''] (A order)
__device__ __nv_bfloat16 g_ai [T_ * KP];            // ctx tokens [t][k''] (A order)
__device__ __nv_bfloat16 g_wb [3 * DM_ * KP];       // qkv weights [mat*768+n][k''] (B order)
__device__ __nv_bfloat16 g_wdb[DM_ * KP];           // dense weights [n][k''] (B order)

// ---------------- packed f32x2 helpers (attn kernel) ----------------
typedef unsigned long long ull;

__device__ __forceinline__ ull pack2(float lo, float hi) {
    ull r;
    asm("mov.b64 %0, {%1, %2};" : "=l"(r) : "f"(lo), "f"(hi));
    return r;
}
__device__ __forceinline__ void unpack2(ull v, float& lo, float& hi) {
    asm("mov.b64 {%0, %1}, %2;" : "=f"(lo), "=f"(hi) : "l"(v));
}
__device__ __forceinline__ void fma2(ull& c, ull a, ull b) {
    asm("fma.rn.f32x2 %0, %1, %2, %3;" : "=l"(c) : "l"(a), "l"(b), "l"(c));
}
__device__ __forceinline__ void mul2(ull& c, ull a) {
    asm("mul.rn.f32x2 %0, %1, %2;" : "=l"(c) : "l"(c), "l"(a));
}
__device__ __forceinline__ void mma44(ull c[8], float4 a, float4 b) {
    ull b0 = pack2(b.x, b.y), b1 = pack2(b.z, b.w);
    ull a0 = pack2(a.x, a.x); fma2(c[0], a0, b0); fma2(c[1], a0, b1);
    ull a1 = pack2(a.y, a.y); fma2(c[2], a1, b0); fma2(c[3], a1, b1);
    ull a2 = pack2(a.z, a.z); fma2(c[4], a2, b0); fma2(c[5], a2, b1);
    ull a3 = pack2(a.w, a.w); fma2(c[6], a3, b0); fma2(c[7], a3, b1);
}

// ---------------- mma.sync / ldmatrix / cp.async helpers ----------------
__device__ __forceinline__ uint32_t smem_u32(const void* p) {
    uint32_t a;
    asm("{ .reg .u64 t; cvta.to.shared.u64 t, %1; cvt.u32.u64 %0, t; }"
        : "=r"(a) : "l"(p));
    return a;
}
__device__ __forceinline__ void ldsm4(uint32_t r[4], uint32_t addr) {
    asm volatile("ldmatrix.sync.aligned.m8n8.x4.shared.b16 {%0,%1,%2,%3}, [%4];"
                 : "=r"(r[0]), "=r"(r[1]), "=r"(r[2]), "=r"(r[3]) : "r"(addr));
}
__device__ __forceinline__ void mma_bf16(float d[4], const uint32_t a[4],
                                         uint32_t b0, uint32_t b1) {
    asm volatile(
        "mma.sync.aligned.m16n8k16.row.col.f32.bf16.bf16.f32 "
        "{%0,%1,%2,%3}, {%4,%5,%6,%7}, {%8,%9}, {%0,%1,%2,%3};"
        : "+f"(d[0]), "+f"(d[1]), "+f"(d[2]), "+f"(d[3])
        : "r"(a[0]), "r"(a[1]), "r"(a[2]), "r"(a[3]), "r"(b0), "r"(b1));
}
__device__ __forceinline__ void cpasync16(uint32_t dst, const void* src) {
    asm volatile("cp.async.cg.shared.global [%0], [%1], 16;\n"
                 :: "r"(dst), "l"(src));
}
#define CP_COMMIT() asm volatile("cp.async.commit_group;\n" ::)
#define CP_WAIT2()  asm volatile("cp.async.wait_group 2;\n" ::)

// triple expansion: A side (ah, ah, al); B side (bh, bl, bh).
// Sum over a triple = ah*bh + ah*bl + al*bh  (split-3, err ~2^-18).
__device__ __forceinline__ void tripleA(float v, __nv_bfloat16* o) {
    __nv_bfloat16 h = __float2bfloat16_rn(v);
    __nv_bfloat16 l = __float2bfloat16_rn(v - __bfloat162float(h));
    o[0] = h; o[1] = h; o[2] = l;
}
__device__ __forceinline__ void tripleB(float v, __nv_bfloat16* o) {
    __nv_bfloat16 h = __float2bfloat16_rn(v);
    __nv_bfloat16 l = __float2bfloat16_rn(v - __bfloat162float(h));
    o[0] = h; o[1] = l; o[2] = h;
}

// ---------------- GEMM geometry ----------------
#define KC      32                  // bf16 per stage (k'' units)
#define NCHUNK  (KP / KC)           // 72
#define ROWB    80                  // 64B data + 16B pad per smem row
#define STAGE_A (128 * ROWB)        // 10240 B
#define STAGE_B (2 * STAGE_A)       // 20480 B per stage (A + B)
#define SMEM_G  (4 * STAGE_B)       // 81920 B

// ====================================================================
// pipelined 128x128xKP bf16 GEMM mainloop (shared by qkv/dense).
// ====================================================================
__device__ __forceinline__ void g_issue(uint32_t smu, int tid, int c,
                                        const __nv_bfloat16* Arows,
                                        const __nv_bfloat16* Brows)
{
    const uint32_t base = smu + (uint32_t)(c & 3) * STAGE_B;
    const int k0 = c * KC;
    #pragma unroll
    for (int r = 0; r < 2; ++r) {
        int idx = tid + r * 256;
        int row = idx >> 2, c16 = idx & 3;
        cpasync16(base + row * ROWB + c16 * 16,
                  Arows + (size_t)row * KP + k0 + c16 * 8);
        cpasync16(base + STAGE_A + row * ROWB + c16 * 16,
                  Brows + (size_t)row * KP + k0 + c16 * 8);
    }
}

__device__ __forceinline__ void gemm_main(const __nv_bfloat16* Arows,
                                          const __nv_bfloat16* Brows,
                                          char* sm, int tid,
                                          float acc[2][8][4])
{
    const int lane = tid & 31, wid = tid >> 5;
    const int wm = wid & 3, wn = wid >> 2;
    const uint32_t smu = smem_u32(sm);

    g_issue(smu, tid, 0, Arows, Brows); CP_COMMIT();
    g_issue(smu, tid, 1, Arows, Brows); CP_COMMIT();
    g_issue(smu, tid, 2, Arows, Brows); CP_COMMIT();

    const uint32_t faoff = (uint32_t)((wm * 32 + (lane & 15)) * ROWB +
                                      ((lane >> 4) & 1) * 16);
    const uint32_t fboff = (uint32_t)(STAGE_A +
                           (wn * 64 + (lane & 7) + ((lane & 16) >> 1)) * ROWB +
                           (lane & 8) * 2);

    for (int c = 0; c < NCHUNK; ++c) {
        CP_WAIT2();
        __syncthreads();
        if (c + 3 < NCHUNK) g_issue(smu, tid, c + 3, Arows, Brows);
        CP_COMMIT();

        const uint32_t sb = smu + (uint32_t)(c & 3) * STAGE_B;
        const uint32_t fa = sb + faoff;
        const uint32_t fb = sb + fboff;
        #pragma unroll
        for (int k16 = 0; k16 < 2; ++k16) {
            uint32_t a0[4], a1[4];
            ldsm4(a0, fa + k16 * 32);
            ldsm4(a1, fa + 16 * ROWB + k16 * 32);
            #pragma unroll
            for (int np = 0; np < 4; ++np) {
                uint32_t bh[4];
                ldsm4(bh, fb + np * 16 * ROWB + k16 * 32);
                mma_bf16(acc[0][np * 2 + 0], a0, bh[0], bh[1]);
                mma_bf16(acc[0][np * 2 + 1], a0, bh[2], bh[3]);
                mma_bf16(acc[1][np * 2 + 0], a1, bh[0], bh[1]);
                mma_bf16(acc[1][np * 2 + 1], a1, bh[2], bh[3]);
            }
        }
    }
}

// ====================================================================
// conversion kernels
// ====================================================================
// x -> g_xi: flat mapping, source index f -> dest index 3f (A order).
// Each thread: 8 source floats -> 24 halves (48 B, 16B-aligned).
__global__ void __launch_bounds__(256)
conv_x(const float* __restrict__ x)
{
    const size_t g = (size_t)blockIdx.x * 256 + threadIdx.x;
    const float* src = x + g * 8;
    uint4 buf4[3];
    __nv_bfloat16* buf = (__nv_bfloat16*)buf4;
    float4 v0 = *(const float4*)(src);
    float4 v1 = *(const float4*)(src + 4);
    tripleA(v0.x, buf + 0);  tripleA(v0.y, buf + 3);
    tripleA(v0.z, buf + 6);  tripleA(v0.w, buf + 9);
    tripleA(v1.x, buf + 12); tripleA(v1.y, buf + 15);
    tripleA(v1.z, buf + 18); tripleA(v1.w, buf + 21);
    uint4* dp = (uint4*)(g_xi + g * 24);
    dp[0] = buf4[0]; dp[1] = buf4[1]; dp[2] = buf4[2];
}

// qkv weights: W[mat][h][e][d] -> g_wb[mat*768 + h*64 + d][3e..] (B order)
__global__ void __launch_bounds__(256)
conv_w(const float* __restrict__ Wq, const float* __restrict__ Wk,
       const float* __restrict__ Wv)
{
    __shared__ float tile[64][65];
    const int e0  = blockIdx.x * 64;
    const int h   = blockIdx.y;
    const int mat = blockIdx.z;
    const float* W = (mat == 0) ? Wq : (mat == 1) ? Wk : Wv;
    const int tid = threadIdx.x;

    #pragma unroll
    for (int r = 0; r < 16; ++r) {
        int idx = tid + r * 256;
        int el = idx >> 6, d = idx & 63;
        tile[el][d] = W[((size_t)h * E_ + e0 + el) * DH_ + d];
    }
    __syncthreads();

    const int d = tid >> 2, eg = tid & 3;
    uint4 buf4[6];
    __nv_bfloat16* buf = (__nv_bfloat16*)buf4;
    #pragma unroll
    for (int i = 0; i < 16; ++i)
        tripleB(tile[eg * 16 + i][d], buf + 3 * i);
    uint4* dp = (uint4*)(g_wb + ((size_t)mat * DM_ + h * 64 + d) * KP +
                         (size_t)(e0 + eg * 16) * 3);
    #pragma unroll
    for (int j = 0; j < 6; ++j) dp[j] = buf4[j];
}

// dense weights: Wd[k][n] -> g_wdb[n][3k..] (B order)
__global__ void __launch_bounds__(256)
conv_wd(const float* __restrict__ Wd)
{
    __shared__ float tile[64][65];
    const int k0 = blockIdx.x * 64;
    const int n0 = blockIdx.y * 64;
    const int tid = threadIdx.x;

    #pragma unroll
    for (int r = 0; r < 16; ++r) {
        int idx = tid + r * 256;
        int kl = idx >> 6, nl = idx & 63;
        tile[kl][nl] = Wd[(size_t)(k0 + kl) * DM_ + n0 + nl];
    }
    __syncthreads();

    const int nl = tid >> 2, kg = tid & 3;
    uint4 buf4[6];
    __nv_bfloat16* buf = (__nv_bfloat16*)buf4;
    #pragma unroll
    for (int i = 0; i < 16; ++i)
        tripleB(tile[kg * 16 + i][nl], buf + 3 * i);
    uint4* dp = (uint4*)(g_wdb + (size_t)(n0 + nl) * KP +
                         (size_t)(k0 + kg * 16) * 3);
    #pragma unroll
    for (int j = 0; j < 6; ++j) dp[j] = buf4[j];
}

// ====================================================================
// K1: QKV projection. grid (32, 6, 3), block 256, smem SMEM_G.
// ====================================================================
__global__ void __launch_bounds__(256, 2)
qkv_mma(const float* __restrict__ bq, const float* __restrict__ bk,
        const float* __restrict__ bv)
{
    extern __shared__ char sm[];
    const int tid = threadIdx.x, lane = tid & 31, wid = tid >> 5;
    const int wm = wid & 3, wn = wid >> 2;

    const int mat = blockIdx.z;
    const float* bias = (mat == 0) ? bq : (mat == 1) ? bk : bv;
    float* outp       = (mat == 0) ? g_Q : (mat == 1) ? g_K : g_V;

    const int t0 = blockIdx.x * 128;
    const int n0 = blockIdx.y * 128;

    float acc[2][8][4];
    #pragma unroll
    for (int i = 0; i < 2; ++i)
        #pragma unroll
        for (int j = 0; j < 8; ++j)
            #pragma unroll
            for (int k = 0; k < 4; ++k) acc[i][j][k] = 0.f;

    gemm_main(g_xi + (size_t)t0 * KP,
              g_wb + ((size_t)mat * DM_ + n0) * KP, sm, tid, acc);

    #pragma unroll
    for (int mi = 0; mi < 2; ++mi) {
        #pragma unroll
        for (int ni = 0; ni < 8; ++ni) {
            const int cl = wn * 64 + ni * 8 + (lane & 3) * 2;
            const int ng = n0 + cl;
            const int h = ng >> 6, d = ng & 63;
            const float b0v = bias[h * DH_ + d];
            const float b1v = bias[h * DH_ + d + 1];
            #pragma unroll
            for (int r8 = 0; r8 < 2; ++r8) {
                const int t = t0 + wm * 32 + mi * 16 + (lane >> 2) + r8 * 8;
                const int bb = t >> 10, ss = t & (S_ - 1);
                float2 o = make_float2(acc[mi][ni][2 * r8] + b0v,
                                       acc[mi][ni][2 * r8 + 1] + b1v);
                *(float2*)(outp + ((size_t)(bb * H_ + h) * S_ + ss) * DH_ + d) = o;
            }
        }
    }
}

// ====================================================================
// K4: output dense. grid (32, 6), block 256, smem SMEM_G.
// ====================================================================
__global__ void __launch_bounds__(256, 2)
dense_mma(const float* __restrict__ bd)
{
    extern __shared__ char sm[];
    const int tid = threadIdx.x, lane = tid & 31, wid = tid >> 5;
    const int wm = wid & 3, wn = wid >> 2;

    const int t0 = blockIdx.x * 128;
    const int n0 = blockIdx.y * 128;

    float acc[2][8][4];
    #pragma unroll
    for (int i = 0; i < 2; ++i)
        #pragma unroll
        for (int j = 0; j < 8; ++j)
            #pragma unroll
            for (int k = 0; k < 4; ++k) acc[i][j][k] = 0.f;

    gemm_main(g_ai + (size_t)t0 * KP, g_wdb + (size_t)n0 * KP, sm, tid, acc);

    #pragma unroll
    for (int mi = 0; mi < 2; ++mi) {
        #pragma unroll
        for (int ni = 0; ni < 8; ++ni) {
            const int cl = wn * 64 + ni * 8 + (lane & 3) * 2;
            const float b0v = bd[n0 + cl];
            const float b1v = bd[n0 + cl + 1];
            #pragma unroll
            for (int r8 = 0; r8 < 2; ++r8) {
                const int t = t0 + wm * 32 + mi * 16 + (lane >> 2) + r8 * 8;
                float2 o = make_float2(acc[mi][ni][2 * r8] + b0v,
                                       acc[mi][ni][2 * r8 + 1] + b1v);
                *(float2*)(g_y + (size_t)t * DM_ + n0 + cl) = o;
            }
        }
    }
}

// ====================================================================
// K2: attention (fp32 f32x2 path; epilogue emits A-order triples).
// ====================================================================
#define ES_STRIDE 68
#define SMEM_ATTN ((3 * 64 * 64 + 64 * ES_STRIDE) * 4)

__global__ void __launch_bounds__(256)
attn_kernel(float* __restrict__ out)
{
    extern __shared__ float smf[];
    float* Qs = smf;
    float* Ks = smf + 4096;
    float* Vs = smf + 8192;
    float* Es = smf + 12288;

    const int b  = blockIdx.z;
    const int h  = blockIdx.y;
    const int q0 = blockIdx.x * 64;
    const int tid = threadIdx.x;
    const int tx = tid & 15, ty = tid >> 4;

    const size_t head_base = (size_t)(b * H_ + h) * S_ * DH_;
    const float* Qb = g_Q + head_base;
    const float* Kb = g_K + head_base;
    const float* Vb = g_V + head_base;

    #pragma unroll
    for (int r = 0; r < 4; r++) {
        int idx = tid + r * 256;
        int m = idx >> 4, dq = (idx & 15) * 4;
        float4 v = *(const float4*)(Qb + (size_t)(q0 + m) * DH_ + dq);
        Qs[(dq + 0) * 64 + m] = v.x;
        Qs[(dq + 1) * 64 + m] = v.y;
        Qs[(dq + 2) * 64 + m] = v.z;
        Qs[(dq + 3) * 64 + m] = v.w;
    }

    ull cacc[8];
    #pragma unroll
    for (int i = 0; i < 8; i++) cacc[i] = 0ull;
    float mrow[4] = {-1e30f, -1e30f, -1e30f, -1e30f};
    float lrow[4] = {0.f, 0.f, 0.f, 0.f};

    for (int kt = 0; kt < 16; kt++) {
        const int n0 = kt * 64;
        __syncthreads();

        #pragma unroll
        for (int r = 0; r < 4; r++) {
            int idx = tid + r * 256;
            int n = idx >> 4, dq = (idx & 15) * 4;
            float4 v = *(const float4*)(Kb + (size_t)(n0 + n) * DH_ + dq);
            Ks[(dq + 0) * 64 + n] = v.x;
            Ks[(dq + 1) * 64 + n] = v.y;
            Ks[(dq + 2) * 64 + n] = v.z;
            Ks[(dq + 3) * 64 + n] = v.w;
            ((float4*)Vs)[idx] = ((const float4*)(Vb + (size_t)n0 * DH_))[idx];
        }
        __syncthreads();

        ull p2[8];
        #pragma unroll
        for (int i = 0; i < 8; i++) p2[i] = 0ull;
        #pragma unroll
        for (int d = 0; d < 64; d++) {
            float4 q4 = *(const float4*)(Qs + d * 64 + ty * 4);
            float4 k4 = *(const float4*)(Ks + d * 64 + tx * 4);
            mma44(p2, q4, k4);
        }

        float p[4][4];
        #pragma unroll
        for (int i = 0; i < 4; i++) {
            unpack2(p2[2 * i],     p[i][0], p[i][1]);
            unpack2(p2[2 * i + 1], p[i][2], p[i][3]);
            #pragma unroll
            for (int j = 0; j < 4; j++) p[i][j] *= SQK;
        }

        #pragma unroll
        for (int i = 0; i < 4; i++) {
            const int s = q0 + ty * 4 + i;
            size_t off = (((size_t)(b * S_ + s)) * H_ + h) * S_ + n0 + tx * 4;
            *(float4*)(out + off) = make_float4(p[i][0], p[i][1], p[i][2], p[i][3]);
        }

        #pragma unroll
        for (int i = 0; i < 4; i++) {
            float pm = fmaxf(fmaxf(p[i][0], p[i][1]), fmaxf(p[i][2], p[i][3]));
            pm = fmaxf(pm, __shfl_xor_sync(0xffffffffu, pm, 1));
            pm = fmaxf(pm, __shfl_xor_sync(0xffffffffu, pm, 2));
            pm = fmaxf(pm, __shfl_xor_sync(0xffffffffu, pm, 4));
            pm = fmaxf(pm, __shfl_xor_sync(0xffffffffu, pm, 8));
            float mnew = fmaxf(mrow[i], pm);
            float f = __expf(mrow[i] - mnew);
            mrow[i] = mnew;
            float e0 = __expf(p[i][0] - mnew);
            float e1 = __expf(p[i][1] - mnew);
            float e2 = __expf(p[i][2] - mnew);
            float e3 = __expf(p[i][3] - mnew);
            float rs = (e0 + e1) + (e2 + e3);
            rs += __shfl_xor_sync(0xffffffffu, rs, 1);
            rs += __shfl_xor_sync(0xffffffffu, rs, 2);
            rs += __shfl_xor_sync(0xffffffffu, rs, 4);
            rs += __shfl_xor_sync(0xffffffffu, rs, 8);
            lrow[i] = lrow[i] * f + rs;
            ull f2 = pack2(f, f);
            mul2(cacc[2 * i], f2);
            mul2(cacc[2 * i + 1], f2);
            *(float4*)(Es + (ty * 4 + i) * ES_STRIDE + tx * 4) =
                make_float4(e0, e1, e2, e3);
        }
        __syncthreads();

        #pragma unroll 4
        for (int n = 0; n < 64; n++) {
            float4 v4 = *(const float4*)(Vs + n * 64 + tx * 4);
            ull b0 = pack2(v4.x, v4.y), b1 = pack2(v4.z, v4.w);
            #pragma unroll
            for (int i = 0; i < 4; i++) {
                float e = Es[(ty * 4 + i) * ES_STRIDE + n];
                ull a2 = pack2(e, e);
                fma2(cacc[2 * i], a2, b0);
                fma2(cacc[2 * i + 1], a2, b1);
            }
        }
    }

    // epilogue: ctx/l -> A-order triples into g_ai[t][k'']
    #pragma unroll
    for (int i = 0; i < 4; i++) {
        const int s = q0 + ty * 4 + i;
        const int t = b * S_ + s;
        float inv = 1.0f / lrow[i];
        float c0, c1, c2, c3;
        unpack2(cacc[2 * i],     c0, c1);
        unpack2(cacc[2 * i + 1], c2, c3);
        // 4 values -> 12 halves (24 B, 8B-aligned): three uint2 stores
        uint2 buf2[3];
        __nv_bfloat16* buf = (__nv_bfloat16*)buf2;
        tripleA(c0 * inv, buf + 0);
        tripleA(c1 * inv, buf + 3);
        tripleA(c2 * inv, buf + 6);
        tripleA(c3 * inv, buf + 9);
        uint2* dp = (uint2*)(g_ai + (size_t)t * KP + (size_t)(h * 64 + tx * 4) * 3);
        dp[0] = buf2[0]; dp[1] = buf2[1]; dp[2] = buf2[2];
        if (tx == 0) {
            g_m[(b * H_ + h) * S_ + s] = mrow[i];
            g_l[(b * H_ + h) * S_ + s] = lrow[i];
        }
    }
}

// ====================================================================
// K3: in-place normalization of the weights region of d_out.
// ====================================================================
__global__ void __launch_bounds__(256)
normw_kernel(float* __restrict__ out)
{
    const int row = blockIdx.x;
    const int h  = row % H_;
    const int bs = row / H_;
    const int s  = bs & (S_ - 1);
    const int b  = bs >> 10;
    const float m    = g_m[(b * H_ + h) * S_ + s];
    const float invl = 1.0f / g_l[(b * H_ + h) * S_ + s];

    size_t base = (size_t)row * S_ + threadIdx.x * 4;
    float4 p = *(float4*)(out + base);
    p.x = __expf(p.x - m) * invl;
    p.y = __expf(p.y - m) * invl;
    p.z = __expf(p.z - m) * invl;
    p.w = __expf(p.w - m) * invl;
    *(float4*)(out + base) = p;
}

// ====================================================================
// K5: LayerNorm. grid T, block 256.
// ====================================================================
__global__ void __launch_bounds__(256)
ln_kernel(const float* __restrict__ gamma, const float* __restrict__ beta,
          float* __restrict__ out)
{
    __shared__ float row[DM_];
    __shared__ float red[8];

    const int t = blockIdx.x;
    const int tid = threadIdx.x;

    float s = 0.f;
    #pragma unroll
    for (int j = 0; j < 3; j++) {
        float v = g_y[(size_t)t * DM_ + tid + j * 256];
        row[tid + j * 256] = v;
        s += v;
    }
    #pragma unroll
    for (int o = 16; o > 0; o >>= 1) s += __shfl_xor_sync(0xffffffffu, s, o);
    if ((tid & 31) == 0) red[tid >> 5] = s;
    __syncthreads();
    float tot = red[0];
    #pragma unroll
    for (int i = 1; i < 8; i++) tot += red[i];
    const float mu = tot * (1.0f / DM_);
    __syncthreads();

    float vs = 0.f;
    #pragma unroll
    for (int j = 0; j < 3; j++) {
        float d = row[tid + j * 256] - mu;
        vs += d * d;
    }
    #pragma unroll
    for (int o = 16; o > 0; o >>= 1) vs += __shfl_xor_sync(0xffffffffu, vs, o);
    if ((tid & 31) == 0) red[tid >> 5] = vs;
    __syncthreads();
    float tv = red[0];
    #pragma unroll
    for (int i = 1; i < 8; i++) tv += red[i];
    const float scale = rsqrtf(tv * (1.0f / DM_) + 1e-12f);

    #pragma unroll
    for (int j = 0; j < 3; j++) {
        const int idx = tid + j * 256;
        out[WOFF + (size_t)t * DM_ + idx] =
            (row[idx] - mu) * scale * gamma[idx] + beta[idx];
    }
}

// ====================================================================
// launch
// ====================================================================
extern "C" void kernel_launch(void* const* d_in, const int* in_sizes, int n_in,
                              void* d_out, int out_size)
{
    (void)in_sizes; (void)n_in; (void)out_size;
    const float* x     = (const float*)d_in[0];
    const float* Wq    = (const float*)d_in[1];
    const float* bq    = (const float*)d_in[2];
    const float* Wk    = (const float*)d_in[3];
    const float* bk    = (const float*)d_in[4];
    const float* Wv    = (const float*)d_in[5];
    const float* bv    = (const float*)d_in[6];
    const float* Wd    = (const float*)d_in[7];
    const float* bd    = (const float*)d_in[8];
    const float* gamma = (const float*)d_in[9];
    const float* beta  = (const float*)d_in[10];
    float* out = (float*)d_out;

    cudaFuncSetAttribute(qkv_mma,
                         cudaFuncAttributeMaxDynamicSharedMemorySize, SMEM_G);
    cudaFuncSetAttribute(dense_mma,
                         cudaFuncAttributeMaxDynamicSharedMemorySize, SMEM_G);
    cudaFuncSetAttribute(attn_kernel,
                         cudaFuncAttributeMaxDynamicSharedMemorySize, SMEM_ATTN);

    conv_x<<<T_ * E_ / 8 / 256, 256>>>(x);
    conv_w<<<dim3(E_ / 64, H_, 3), 256>>>(Wq, Wk, Wv);
    conv_wd<<<dim3(DM_ / 64, DM_ / 64), 256>>>(Wd);

    qkv_mma<<<dim3(T_ / 128, DM_ / 128, 3), 256, SMEM_G>>>(bq, bk, bv);

    attn_kernel<<<dim3(S_ / 64, H_, B_), 256, SMEM_ATTN>>>(out);

    normw_kernel<<<B_ * S_ * H_, 256>>>(out);

    dense_mma<<<dim3(T_ / 128, DM_ / 128), 256, SMEM_G>>>(bd);

    ln_kernel<<<T_, 256>>>(gamma, beta, out);
}

// round 10
// speedup vs baseline: 1.9367x; 1.3682x over previous
#include <cuda_runtime.h>
#include <cuda_bf16.h>
#include <cstdint>
#include <cstddef>

// ---------------- problem constants ----------------
#define B_   4
#define S_   1024
#define H_   12
#define DH_  64
#define E_   768
#define DM_  768
#define T_   (B_ * S_)            // 4096 tokens
#define KP   2304                 // triple-expanded K for the big GEMMs
#define KH   192                  // triple-expanded head dim (3*64)
#define SQK  0.125f               // 1/sqrt(64)
#define WOFF ((size_t)B_ * S_ * H_ * S_)   // start of y in d_out

// ---------------- scratch (device globals; no allocation) ----------------
__device__ float g_y [T_ * DM_];
__device__ float g_m [B_ * H_ * S_];
__device__ float g_l [B_ * H_ * S_];
// triple-expanded bf16 operands
__device__ __nv_bfloat16 g_xi [T_ * KP];            // x tokens (A order)
__device__ __nv_bfloat16 g_ai [T_ * KP];            // ctx tokens (A order)
__device__ __nv_bfloat16 g_wb [3 * DM_ * KP];       // qkv weights (B order)
__device__ __nv_bfloat16 g_wdb[DM_ * KP];           // dense weights (B order)
// attention operands (written by qkv epilogue)
__device__ __nv_bfloat16 g_Qi [B_ * H_ * S_ * KH];  // Q A-triples [bh][s][192]
__device__ __nv_bfloat16 g_Ki [B_ * H_ * S_ * KH];  // K B-triples [bh][s][192]
__device__ __nv_bfloat16 g_Vt [B_ * H_ * DH_ * 3 * S_]; // V B-triples [bh][d][3s]

// ---------------- mma.sync / ldmatrix / cp.async helpers ----------------
typedef unsigned long long ull;

__device__ __forceinline__ uint32_t smem_u32(const void* p) {
    uint32_t a;
    asm("{ .reg .u64 t; cvta.to.shared.u64 t, %1; cvt.u32.u64 %0, t; }"
        : "=r"(a) : "l"(p));
    return a;
}
__device__ __forceinline__ void ldsm4(uint32_t r[4], uint32_t addr) {
    asm volatile("ldmatrix.sync.aligned.m8n8.x4.shared.b16 {%0,%1,%2,%3}, [%4];"
                 : "=r"(r[0]), "=r"(r[1]), "=r"(r[2]), "=r"(r[3]) : "r"(addr));
}
__device__ __forceinline__ void mma_bf16(float d[4], const uint32_t a[4],
                                         uint32_t b0, uint32_t b1) {
    asm volatile(
        "mma.sync.aligned.m16n8k16.row.col.f32.bf16.bf16.f32 "
        "{%0,%1,%2,%3}, {%4,%5,%6,%7}, {%8,%9}, {%0,%1,%2,%3};"
        : "+f"(d[0]), "+f"(d[1]), "+f"(d[2]), "+f"(d[3])
        : "r"(a[0]), "r"(a[1]), "r"(a[2]), "r"(a[3]), "r"(b0), "r"(b1));
}
__device__ __forceinline__ void cpasync16(uint32_t dst, const void* src) {
    asm volatile("cp.async.cg.shared.global [%0], [%1], 16;\n"
                 :: "r"(dst), "l"(src));
}
#define CP_COMMIT() asm volatile("cp.async.commit_group;\n" ::)
#define CP_WAIT2()  asm volatile("cp.async.wait_group 2;\n" ::)
#define CP_WAIT1()  asm volatile("cp.async.wait_group 1;\n" ::)

// triple expansion: A side (h,h,l); B side (h,l,h).
__device__ __forceinline__ void tripleA(float v, __nv_bfloat16* o) {
    __nv_bfloat16 h = __float2bfloat16_rn(v);
    __nv_bfloat16 l = __float2bfloat16_rn(v - __bfloat162float(h));
    o[0] = h; o[1] = h; o[2] = l;
}
__device__ __forceinline__ void tripleB(float v, __nv_bfloat16* o) {
    __nv_bfloat16 h = __float2bfloat16_rn(v);
    __nv_bfloat16 l = __float2bfloat16_rn(v - __bfloat162float(h));
    o[0] = h; o[1] = l; o[2] = h;
}
// packed pair-of-triples (two consecutive values -> 3 uint32)
__device__ __forceinline__ void packA2(float v0, float v1, uint32_t u[3]) {
    __nv_bfloat16 h0 = __float2bfloat16_rn(v0);
    __nv_bfloat16 l0 = __float2bfloat16_rn(v0 - __bfloat162float(h0));
    __nv_bfloat16 h1 = __float2bfloat16_rn(v1);
    __nv_bfloat16 l1 = __float2bfloat16_rn(v1 - __bfloat162float(h1));
    uint32_t H0 = __bfloat16_as_ushort(h0), L0 = __bfloat16_as_ushort(l0);
    uint32_t H1 = __bfloat16_as_ushort(h1), L1 = __bfloat16_as_ushort(l1);
    u[0] = H0 | (H0 << 16); u[1] = L0 | (H1 << 16); u[2] = H1 | (L1 << 16);
}
__device__ __forceinline__ void packB2(float v0, float v1, uint32_t u[3]) {
    __nv_bfloat16 h0 = __float2bfloat16_rn(v0);
    __nv_bfloat16 l0 = __float2bfloat16_rn(v0 - __bfloat162float(h0));
    __nv_bfloat16 h1 = __float2bfloat16_rn(v1);
    __nv_bfloat16 l1 = __float2bfloat16_rn(v1 - __bfloat162float(h1));
    uint32_t H0 = __bfloat16_as_ushort(h0), L0 = __bfloat16_as_ushort(l0);
    uint32_t H1 = __bfloat16_as_ushort(h1), L1 = __bfloat16_as_ushort(l1);
    u[0] = H0 | (L0 << 16); u[1] = H0 | (H1 << 16); u[2] = L1 | (H1 << 16);
}

// ---------------- GEMM geometry (qkv/dense, unchanged from R9) ----------------
#define KC      32
#define NCHUNK  (KP / KC)           // 72
#define ROWB    80
#define STAGE_A (128 * ROWB)
#define STAGE_B (2 * STAGE_A)
#define SMEM_G  (4 * STAGE_B)       // 81920 B

__device__ __forceinline__ void g_issue(uint32_t smu, int tid, int c,
                                        const __nv_bfloat16* Arows,
                                        const __nv_bfloat16* Brows)
{
    const uint32_t base = smu + (uint32_t)(c & 3) * STAGE_B;
    const int k0 = c * KC;
    #pragma unroll
    for (int r = 0; r < 2; ++r) {
        int idx = tid + r * 256;
        int row = idx >> 2, c16 = idx & 3;
        cpasync16(base + row * ROWB + c16 * 16,
                  Arows + (size_t)row * KP + k0 + c16 * 8);
        cpasync16(base + STAGE_A + row * ROWB + c16 * 16,
                  Brows + (size_t)row * KP + k0 + c16 * 8);
    }
}

__device__ __forceinline__ void gemm_main(const __nv_bfloat16* Arows,
                                          const __nv_bfloat16* Brows,
                                          char* sm, int tid,
                                          float acc[2][8][4])
{
    const int lane = tid & 31, wid = tid >> 5;
    const int wm = wid & 3, wn = wid >> 2;
    const uint32_t smu = smem_u32(sm);

    g_issue(smu, tid, 0, Arows, Brows); CP_COMMIT();
    g_issue(smu, tid, 1, Arows, Brows); CP_COMMIT();
    g_issue(smu, tid, 2, Arows, Brows); CP_COMMIT();

    const uint32_t faoff = (uint32_t)((wm * 32 + (lane & 15)) * ROWB +
                                      ((lane >> 4) & 1) * 16);
    const uint32_t fboff = (uint32_t)(STAGE_A +
                           (wn * 64 + (lane & 7) + ((lane & 16) >> 1)) * ROWB +
                           (lane & 8) * 2);

    for (int c = 0; c < NCHUNK; ++c) {
        CP_WAIT2();
        __syncthreads();
        if (c + 3 < NCHUNK) g_issue(smu, tid, c + 3, Arows, Brows);
        CP_COMMIT();

        const uint32_t sb = smu + (uint32_t)(c & 3) * STAGE_B;
        const uint32_t fa = sb + faoff;
        const uint32_t fb = sb + fboff;
        #pragma unroll
        for (int k16 = 0; k16 < 2; ++k16) {
            uint32_t a0[4], a1[4];
            ldsm4(a0, fa + k16 * 32);
            ldsm4(a1, fa + 16 * ROWB + k16 * 32);
            #pragma unroll
            for (int np = 0; np < 4; ++np) {
                uint32_t bh[4];
                ldsm4(bh, fb + np * 16 * ROWB + k16 * 32);
                mma_bf16(acc[0][np * 2 + 0], a0, bh[0], bh[1]);
                mma_bf16(acc[0][np * 2 + 1], a0, bh[2], bh[3]);
                mma_bf16(acc[1][np * 2 + 0], a1, bh[0], bh[1]);
                mma_bf16(acc[1][np * 2 + 1], a1, bh[2], bh[3]);
            }
        }
    }
}

// ====================================================================
// conversion kernels (unchanged from R9)
// ====================================================================
__global__ void __launch_bounds__(256)
conv_x(const float* __restrict__ x)
{
    const size_t g = (size_t)blockIdx.x * 256 + threadIdx.x;
    const float* src = x + g * 8;
    uint4 buf4[3];
    __nv_bfloat16* buf = (__nv_bfloat16*)buf4;
    float4 v0 = *(const float4*)(src);
    float4 v1 = *(const float4*)(src + 4);
    tripleA(v0.x, buf + 0);  tripleA(v0.y, buf + 3);
    tripleA(v0.z, buf + 6);  tripleA(v0.w, buf + 9);
    tripleA(v1.x, buf + 12); tripleA(v1.y, buf + 15);
    tripleA(v1.z, buf + 18); tripleA(v1.w, buf + 21);
    uint4* dp = (uint4*)(g_xi + g * 24);
    dp[0] = buf4[0]; dp[1] = buf4[1]; dp[2] = buf4[2];
}

__global__ void __launch_bounds__(256)
conv_w(const float* __restrict__ Wq, const float* __restrict__ Wk,
       const float* __restrict__ Wv)
{
    __shared__ float tile[64][65];
    const int e0  = blockIdx.x * 64;
    const int h   = blockIdx.y;
    const int mat = blockIdx.z;
    const float* W = (mat == 0) ? Wq : (mat == 1) ? Wk : Wv;
    const int tid = threadIdx.x;

    #pragma unroll
    for (int r = 0; r < 16; ++r) {
        int idx = tid + r * 256;
        int el = idx >> 6, d = idx & 63;
        tile[el][d] = W[((size_t)h * E_ + e0 + el) * DH_ + d];
    }
    __syncthreads();

    const int d = tid >> 2, eg = tid & 3;
    uint4 buf4[6];
    __nv_bfloat16* buf = (__nv_bfloat16*)buf4;
    #pragma unroll
    for (int i = 0; i < 16; ++i)
        tripleB(tile[eg * 16 + i][d], buf + 3 * i);
    uint4* dp = (uint4*)(g_wb + ((size_t)mat * DM_ + h * 64 + d) * KP +
                         (size_t)(e0 + eg * 16) * 3);
    #pragma unroll
    for (int j = 0; j < 6; ++j) dp[j] = buf4[j];
}

__global__ void __launch_bounds__(256)
conv_wd(const float* __restrict__ Wd)
{
    __shared__ float tile[64][65];
    const int k0 = blockIdx.x * 64;
    const int n0 = blockIdx.y * 64;
    const int tid = threadIdx.x;

    #pragma unroll
    for (int r = 0; r < 16; ++r) {
        int idx = tid + r * 256;
        int kl = idx >> 6, nl = idx & 63;
        tile[kl][nl] = Wd[(size_t)(k0 + kl) * DM_ + n0 + nl];
    }
    __syncthreads();

    const int nl = tid >> 2, kg = tid & 3;
    uint4 buf4[6];
    __nv_bfloat16* buf = (__nv_bfloat16*)buf4;
    #pragma unroll
    for (int i = 0; i < 16; ++i)
        tripleB(tile[kg * 16 + i][nl], buf + 3 * i);
    uint4* dp = (uint4*)(g_wdb + (size_t)(n0 + nl) * KP +
                         (size_t)(k0 + kg * 16) * 3);
    #pragma unroll
    for (int j = 0; j < 6; ++j) dp[j] = buf4[j];
}

// ====================================================================
// K1: QKV projection. Epilogue writes attention-ready triples:
//   Q -> g_Qi (A-triples), K -> g_Ki (B-triples), V -> g_Vt (B-triples,
//   transposed to [bh][d][3s]).
// ====================================================================
__global__ void __launch_bounds__(256, 2)
qkv_mma(const float* __restrict__ bq, const float* __restrict__ bk,
        const float* __restrict__ bv)
{
    extern __shared__ char sm[];
    const int tid = threadIdx.x, lane = tid & 31, wid = tid >> 5;
    const int wm = wid & 3, wn = wid >> 2;

    const int mat = blockIdx.z;
    const float* bias = (mat == 0) ? bq : (mat == 1) ? bk : bv;

    const int t0 = blockIdx.x * 128;
    const int n0 = blockIdx.y * 128;

    float acc[2][8][4];
    #pragma unroll
    for (int i = 0; i < 2; ++i)
        #pragma unroll
        for (int j = 0; j < 8; ++j)
            #pragma unroll
            for (int k = 0; k < 4; ++k) acc[i][j][k] = 0.f;

    gemm_main(g_xi + (size_t)t0 * KP,
              g_wb + ((size_t)mat * DM_ + n0) * KP, sm, tid, acc);

    #pragma unroll
    for (int mi = 0; mi < 2; ++mi) {
        #pragma unroll
        for (int ni = 0; ni < 8; ++ni) {
            const int cl = wn * 64 + ni * 8 + (lane & 3) * 2;
            const int ng = n0 + cl;
            const int h = ng >> 6, d = ng & 63;
            const float b0v = bias[h * DH_ + d];
            const float b1v = bias[h * DH_ + d + 1];
            #pragma unroll
            for (int r8 = 0; r8 < 2; ++r8) {
                const int t = t0 + wm * 32 + mi * 16 + (lane >> 2) + r8 * 8;
                const int bb = t >> 10, ss = t & (S_ - 1);
                const float v0 = acc[mi][ni][2 * r8] + b0v;
                const float v1 = acc[mi][ni][2 * r8 + 1] + b1v;
                if (mat == 0) {
                    uint32_t u[3];
                    packA2(v0, v1, u);
                    uint32_t* dp = (uint32_t*)(g_Qi +
                        ((size_t)(bb * H_ + h) * S_ + ss) * KH + d * 3);
                    dp[0] = u[0]; dp[1] = u[1]; dp[2] = u[2];
                } else if (mat == 1) {
                    uint32_t u[3];
                    packB2(v0, v1, u);
                    uint32_t* dp = (uint32_t*)(g_Ki +
                        ((size_t)(bb * H_ + h) * S_ + ss) * KH + d * 3);
                    dp[0] = u[0]; dp[1] = u[1]; dp[2] = u[2];
                } else {
                    __nv_bfloat16 tr[3];
                    __nv_bfloat16* vp = g_Vt +
                        ((size_t)(bb * H_ + h) * DH_ + d) * (3 * S_) + 3 * ss;
                    tripleB(v0, tr);
                    vp[0] = tr[0]; vp[1] = tr[1]; vp[2] = tr[2];
                    vp += 3 * S_;
                    tripleB(v1, tr);
                    vp[0] = tr[0]; vp[1] = tr[1]; vp[2] = tr[2];
                }
            }
        }
    }
}

// ====================================================================
// K4: output dense (unchanged from R9).
// ====================================================================
__global__ void __launch_bounds__(256, 2)
dense_mma(const float* __restrict__ bd)
{
    extern __shared__ char sm[];
    const int tid = threadIdx.x, lane = tid & 31, wid = tid >> 5;
    const int wm = wid & 3, wn = wid >> 2;

    const int t0 = blockIdx.x * 128;
    const int n0 = blockIdx.y * 128;

    float acc[2][8][4];
    #pragma unroll
    for (int i = 0; i < 2; ++i)
        #pragma unroll
        for (int j = 0; j < 8; ++j)
            #pragma unroll
            for (int k = 0; k < 4; ++k) acc[i][j][k] = 0.f;

    gemm_main(g_ai + (size_t)t0 * KP, g_wdb + (size_t)n0 * KP, sm, tid, acc);

    #pragma unroll
    for (int mi = 0; mi < 2; ++mi) {
        #pragma unroll
        for (int ni = 0; ni < 8; ++ni) {
            const int cl = wn * 64 + ni * 8 + (lane & 3) * 2;
            const float b0v = bd[n0 + cl];
            const float b1v = bd[n0 + cl + 1];
            #pragma unroll
            for (int r8 = 0; r8 < 2; ++r8) {
                const int t = t0 + wm * 32 + mi * 16 + (lane >> 2) + r8 * 8;
                float2 o = make_float2(acc[mi][ni][2 * r8] + b0v,
                                       acc[mi][ni][2 * r8 + 1] + b1v);
                *(float2*)(g_y + (size_t)t * DM_ + n0 + cl) = o;
            }
        }
    }
}

// ====================================================================
// K2: attention on mma.sync with split-3 triples.
// grid (8, 12, 4), block 256 (8 warps x 16 q-rows), smem 204800 B.
// ====================================================================
#define ASTR   400
#define QS_OFF 0u
#define KS_OFF 51200u
#define VS_OFF 102400u
#define PS_OFF 153600u
#define SMEM_ATT 204800

__device__ __forceinline__ void attn_issue(uint32_t smu, int tid, int kt,
                                           const __nv_bfloat16* Ki_h,
                                           const __nv_bfloat16* Vt_h)
{
    if (kt >= 16) return;
    const uint32_t kb = smu + KS_OFF + (uint32_t)(kt & 1) * 25600u;
    const uint32_t vb = smu + VS_OFF + (uint32_t)(kt & 1) * 25600u;
    #pragma unroll
    for (int r = 0; r < 6; ++r) {
        int idx = tid + r * 256;
        int row = idx / 24, col = idx - row * 24;
        cpasync16(kb + row * ASTR + col * 16,
                  Ki_h + ((size_t)(kt * 64 + row)) * KH + col * 8);
        cpasync16(vb + row * ASTR + col * 16,
                  Vt_h + (size_t)row * (3 * S_) + kt * 192 + col * 8);
    }
}

__global__ void __launch_bounds__(256)
attn_mma(float* __restrict__ out)
{
    extern __shared__ char sm[];
    const int tid = threadIdx.x, lane = tid & 31, wid = tid >> 5;
    const int b = blockIdx.z, h = blockIdx.y;
    const int q0 = blockIdx.x * 128;
    const int bh = b * H_ + h;
    const __nv_bfloat16* Qi_h = g_Qi + (size_t)bh * S_ * KH;
    const __nv_bfloat16* Ki_h = g_Ki + (size_t)bh * S_ * KH;
    const __nv_bfloat16* Vt_h = g_Vt + (size_t)bh * DH_ * (3 * S_);
    const uint32_t smu = smem_u32(sm);

    // stage Q (once) + K/V stage 0 into group 0; K/V stage 1 into group 1
    #pragma unroll
    for (int r = 0; r < 12; ++r) {
        int idx = tid + r * 256;
        int row = idx / 24, col = idx - row * 24;
        cpasync16(smu + QS_OFF + row * ASTR + col * 16,
                  Qi_h + (size_t)(q0 + row) * KH + col * 8);
    }
    attn_issue(smu, tid, 0, Ki_h, Vt_h);
    CP_COMMIT();
    attn_issue(smu, tid, 1, Ki_h, Vt_h);
    CP_COMMIT();

    const uint32_t faoff = (uint32_t)((wid * 16 + (lane & 15)) * ASTR +
                                      ((lane >> 4) & 1) * 16);
    const uint32_t fboff = (uint32_t)(((lane & 7) + ((lane & 16) >> 1)) * ASTR +
                                      (lane & 8) * 2);

    float ctx[8][4];
    #pragma unroll
    for (int i = 0; i < 8; ++i)
        #pragma unroll
        for (int j = 0; j < 4; ++j) ctx[i][j] = 0.f;
    float m0 = -1e30f, m1 = -1e30f, l0 = 0.f, l1 = 0.f;

    const int r0 = lane >> 2;
    const int srow0 = q0 + wid * 16 + r0;       // rows srow0 and srow0+8
    float* orow0 = out + ((size_t)(b * S_ + srow0) * H_ + h) * S_;
    float* orow1 = out + ((size_t)(b * S_ + srow0 + 8) * H_ + h) * S_;

    for (int kt = 0; kt < 16; ++kt) {
        CP_WAIT1();
        __syncthreads();

        const uint32_t kb = smu + KS_OFF + (uint32_t)(kt & 1) * 25600u;
        const uint32_t vb = smu + VS_OFF + (uint32_t)(kt & 1) * 25600u;

        // ---- QK^T over k''=192 ----
        float p[8][4];
        #pragma unroll
        for (int i = 0; i < 8; ++i)
            #pragma unroll
            for (int j = 0; j < 4; ++j) p[i][j] = 0.f;
        #pragma unroll
        for (int k16 = 0; k16 < 12; ++k16) {
            uint32_t a[4];
            ldsm4(a, smu + QS_OFF + faoff + k16 * 32);
            #pragma unroll
            for (int np = 0; np < 4; ++np) {
                uint32_t bv[4];
                ldsm4(bv, kb + fboff + np * 16 * ASTR + k16 * 32);
                mma_bf16(p[np * 2 + 0], a, bv[0], bv[1]);
                mma_bf16(p[np * 2 + 1], a, bv[2], bv[3]);
            }
        }

        // ---- scale + write raw scores ----
        #pragma unroll
        for (int ni = 0; ni < 8; ++ni) {
            #pragma unroll
            for (int j = 0; j < 4; ++j) p[ni][j] *= SQK;
            const int c = kt * 64 + ni * 8 + (lane & 3) * 2;
            *(float2*)(orow0 + c) = make_float2(p[ni][0], p[ni][1]);
            *(float2*)(orow1 + c) = make_float2(p[ni][2], p[ni][3]);
        }

        // ---- online softmax; P-triples into Ps ----
        float mx0 = -1e30f, mx1 = -1e30f;
        #pragma unroll
        for (int ni = 0; ni < 8; ++ni) {
            mx0 = fmaxf(mx0, fmaxf(p[ni][0], p[ni][1]));
            mx1 = fmaxf(mx1, fmaxf(p[ni][2], p[ni][3]));
        }
        mx0 = fmaxf(mx0, __shfl_xor_sync(0xffffffffu, mx0, 1));
        mx0 = fmaxf(mx0, __shfl_xor_sync(0xffffffffu, mx0, 2));
        mx1 = fmaxf(mx1, __shfl_xor_sync(0xffffffffu, mx1, 1));
        mx1 = fmaxf(mx1, __shfl_xor_sync(0xffffffffu, mx1, 2));
        const float mn0 = fmaxf(m0, mx0), mn1 = fmaxf(m1, mx1);
        const float f0 = __expf(m0 - mn0), f1 = __expf(m1 - mn1);
        m0 = mn0; m1 = mn1;

        float s0 = 0.f, s1 = 0.f;
        const uint32_t psrow0 = smu + PS_OFF + (wid * 16 + r0) * ASTR;
        const uint32_t psrow1 = psrow0 + 8 * ASTR;
        #pragma unroll
        for (int ni = 0; ni < 8; ++ni) {
            const float e0 = __expf(p[ni][0] - mn0);
            const float e1 = __expf(p[ni][1] - mn0);
            const float e2 = __expf(p[ni][2] - mn1);
            const float e3 = __expf(p[ni][3] - mn1);
            s0 += e0 + e1; s1 += e2 + e3;
            const int cb = (ni * 8 + (lane & 3) * 2) * 6;   // byte offset 6*c
            uint32_t u[3];
            packA2(e0, e1, u);
            *(uint32_t*)(sm + (psrow0 - smu) + cb + 0) = u[0];
            *(uint32_t*)(sm + (psrow0 - smu) + cb + 4) = u[1];
            *(uint32_t*)(sm + (psrow0 - smu) + cb + 8) = u[2];
            packA2(e2, e3, u);
            *(uint32_t*)(sm + (psrow1 - smu) + cb + 0) = u[0];
            *(uint32_t*)(sm + (psrow1 - smu) + cb + 4) = u[1];
            *(uint32_t*)(sm + (psrow1 - smu) + cb + 8) = u[2];
        }
        s0 += __shfl_xor_sync(0xffffffffu, s0, 1);
        s0 += __shfl_xor_sync(0xffffffffu, s0, 2);
        s1 += __shfl_xor_sync(0xffffffffu, s1, 1);
        s1 += __shfl_xor_sync(0xffffffffu, s1, 2);
        l0 = l0 * f0 + s0;
        l1 = l1 * f1 + s1;
        #pragma unroll
        for (int ni = 0; ni < 8; ++ni) {
            ctx[ni][0] *= f0; ctx[ni][1] *= f0;
            ctx[ni][2] *= f1; ctx[ni][3] *= f1;
        }
        __syncthreads();   // Ps visible to all warps

        // ---- PV over n''=192 ----
        #pragma unroll
        for (int k16 = 0; k16 < 12; ++k16) {
            uint32_t a[4];
            ldsm4(a, smu + PS_OFF + faoff + k16 * 32);
            #pragma unroll
            for (int np = 0; np < 4; ++np) {
                uint32_t bv[4];
                ldsm4(bv, vb + fboff + np * 16 * ASTR + k16 * 32);
                mma_bf16(ctx[np * 2 + 0], a, bv[0], bv[1]);
                mma_bf16(ctx[np * 2 + 1], a, bv[2], bv[3]);
            }
        }
        __syncthreads();   // everyone done with Ks/Vs/Ps this stage

        attn_issue(smu, tid, kt + 2, Ki_h, Vt_h);
        CP_COMMIT();
    }

    // ---- epilogue: ctx/l -> A-triples into g_ai; store m,l ----
    const float inv0 = 1.f / l0, inv1 = 1.f / l1;
    const int t0row = b * S_ + srow0;
    #pragma unroll
    for (int ni = 0; ni < 8; ++ni) {
        const int d = ni * 8 + (lane & 3) * 2;
        uint32_t u[3];
        packA2(ctx[ni][0] * inv0, ctx[ni][1] * inv0, u);
        uint32_t* dp = (uint32_t*)(g_ai + (size_t)t0row * KP + (h * 64 + d) * 3);
        dp[0] = u[0]; dp[1] = u[1]; dp[2] = u[2];
        packA2(ctx[ni][2] * inv1, ctx[ni][3] * inv1, u);
        dp = (uint32_t*)(g_ai + (size_t)(t0row + 8) * KP + (h * 64 + d) * 3);
        dp[0] = u[0]; dp[1] = u[1]; dp[2] = u[2];
    }
    if ((lane & 3) == 0) {
        g_m[(size_t)bh * S_ + (srow0 - q0) + q0] = m0;
        g_l[(size_t)bh * S_ + (srow0 - q0) + q0] = l0;
        g_m[(size_t)bh * S_ + (srow0 - q0) + q0 + 8] = m1;
        g_l[(size_t)bh * S_ + (srow0 - q0) + q0 + 8] = l1;
    }
}

// ====================================================================
// K3: in-place normalization of the weights region of d_out.
// ====================================================================
__global__ void __launch_bounds__(256)
normw_kernel(float* __restrict__ out)
{
    const int row = blockIdx.x;
    const int h  = row % H_;
    const int bs = row / H_;
    const int s  = bs & (S_ - 1);
    const int b  = bs >> 10;
    const float m    = g_m[(b * H_ + h) * S_ + s];
    const float invl = 1.0f / g_l[(b * H_ + h) * S_ + s];

    size_t base = (size_t)row * S_ + threadIdx.x * 4;
    float4 p = *(float4*)(out + base);
    p.x = __expf(p.x - m) * invl;
    p.y = __expf(p.y - m) * invl;
    p.z = __expf(p.z - m) * invl;
    p.w = __expf(p.w - m) * invl;
    *(float4*)(out + base) = p;
}

// ====================================================================
// K5: LayerNorm. grid T, block 256.
// ====================================================================
__global__ void __launch_bounds__(256)
ln_kernel(const float* __restrict__ gamma, const float* __restrict__ beta,
          float* __restrict__ out)
{
    __shared__ float row[DM_];
    __shared__ float red[8];

    const int t = blockIdx.x;
    const int tid = threadIdx.x;

    float s = 0.f;
    #pragma unroll
    for (int j = 0; j < 3; j++) {
        float v = g_y[(size_t)t * DM_ + tid + j * 256];
        row[tid + j * 256] = v;
        s += v;
    }
    #pragma unroll
    for (int o = 16; o > 0; o >>= 1) s += __shfl_xor_sync(0xffffffffu, s, o);
    if ((tid & 31) == 0) red[tid >> 5] = s;
    __syncthreads();
    float tot = red[0];
    #pragma unroll
    for (int i = 1; i < 8; i++) tot += red[i];
    const float mu = tot * (1.0f / DM_);
    __syncthreads();

    float vs = 0.f;
    #pragma unroll
    for (int j = 0; j < 3; j++) {
        float d = row[tid + j * 256] - mu;
        vs += d * d;
    }
    #pragma unroll
    for (int o = 16; o > 0; o >>= 1) vs += __shfl_xor_sync(0xffffffffu, vs, o);
    if ((tid & 31) == 0) red[tid >> 5] = vs;
    __syncthreads();
    float tv = red[0];
    #pragma unroll
    for (int i = 1; i < 8; i++) tv += red[i];
    const float scale = rsqrtf(tv * (1.0f / DM_) + 1e-12f);

    #pragma unroll
    for (int j = 0; j < 3; j++) {
        const int idx = tid + j * 256;
        out[WOFF + (size_t)t * DM_ + idx] =
            (row[idx] - mu) * scale * gamma[idx] + beta[idx];
    }
}

// ====================================================================
// launch
// ====================================================================
extern "C" void kernel_launch(void* const* d_in, const int* in_sizes, int n_in,
                              void* d_out, int out_size)
{
    (void)in_sizes; (void)n_in; (void)out_size;
    const float* x     = (const float*)d_in[0];
    const float* Wq    = (const float*)d_in[1];
    const float* bq    = (const float*)d_in[2];
    const float* Wk    = (const float*)d_in[3];
    const float* bk    = (const float*)d_in[4];
    const float* Wv    = (const float*)d_in[5];
    const float* bv    = (const float*)d_in[6];
    const float* Wd    = (const float*)d_in[7];
    const float* bd    = (const float*)d_in[8];
    const float* gamma = (const float*)d_in[9];
    const float* beta  = (const float*)d_in[10];
    float* out = (float*)d_out;

    cudaFuncSetAttribute(qkv_mma,
                         cudaFuncAttributeMaxDynamicSharedMemorySize, SMEM_G);
    cudaFuncSetAttribute(dense_mma,
                         cudaFuncAttributeMaxDynamicSharedMemorySize, SMEM_G);
    cudaFuncSetAttribute(attn_mma,
                         cudaFuncAttributeMaxDynamicSharedMemorySize, SMEM_ATT);

    conv_x<<<T_ * E_ / 8 / 256, 256>>>(x);
    conv_w<<<dim3(E_ / 64, H_, 3), 256>>>(Wq, Wk, Wv);
    conv_wd<<<dim3(DM_ / 64, DM_ / 64), 256>>>(Wd);

    qkv_mma<<<dim3(T_ / 128, DM_ / 128, 3), 256, SMEM_G>>>(bq, bk, bv);

    attn_mma<<<dim3(S_ / 128, H_, B_), 256, SMEM_ATT>>>(out);

    normw_kernel<<<B_ * S_ * H_, 256>>>(out);

    dense_mma<<<dim3(T_ / 128, DM_ / 128), 256, SMEM_G>>>(bd);

    ln_kernel<<<T_, 256>>>(gamma, beta, out);
}